// round 6
// baseline (speedup 1.0000x reference)
#include <cuda_runtime.h>
#include <math.h>

#define TDIM   2048
#define BDIM   2
#define DMODEL 1024
#define NH     16
#define DH     64
#define WIN    128
#define MTOT   (BDIM*TDIM)          // 4096 rows

// -------- scratch (device globals: allocation-free) --------
__device__ float g_q [MTOT*DMODEL];
__device__ float g_k [MTOT*DMODEL];
__device__ float g_v [MTOT*DMODEL];
__device__ float g_ao[MTOT*DMODEL];
__device__ float g_cos[TDIM*32];
__device__ float g_sin[TDIM*32];

// ============================================================
// SGEMM: C[m][n] = sum_k A[m][k] * W[n][k]  (+bias), K=N=1024
// BM=BN=128, BK=8, 256 threads, 8x8 microtile,
// double-buffered smem (single barrier per K-step).
// ============================================================
template<bool HASBIAS>
__device__ __forceinline__ void sgemm_body(
    const float* __restrict__ A, const float* __restrict__ W,
    float* __restrict__ C, const float* __restrict__ bias)
{
    __shared__ float As[2][8][132];
    __shared__ float Bs[2][8][132];

    const int tid  = threadIdx.x;
    const int brow = blockIdx.y * 128;
    const int bcol = blockIdx.x * 128;

    const int lrow = tid >> 1;          // 0..127
    const int lk   = (tid & 1) * 4;     // 0 or 4

    const float* Ag = A + (brow + lrow) * DMODEL + lk;
    const float* Wg = W + (bcol + lrow) * DMODEL + lk;

    const int trow = (tid >> 4) * 8;    // 0..120
    const int tcol = (tid & 15) * 8;    // 0..120

    float acc[8][8];
    #pragma unroll
    for (int i = 0; i < 8; i++)
        #pragma unroll
        for (int j = 0; j < 8; j++) acc[i][j] = 0.0f;

    float4 a4 = *(const float4*)Ag;
    float4 b4 = *(const float4*)Wg;
    As[0][lk+0][lrow] = a4.x; As[0][lk+1][lrow] = a4.y;
    As[0][lk+2][lrow] = a4.z; As[0][lk+3][lrow] = a4.w;
    Bs[0][lk+0][lrow] = b4.x; Bs[0][lk+1][lrow] = b4.y;
    Bs[0][lk+2][lrow] = b4.z; Bs[0][lk+3][lrow] = b4.w;
    __syncthreads();

    int buf = 0;
    for (int k0 = 0; k0 < DMODEL; k0 += 8) {
        const bool more = (k0 + 8 < DMODEL);
        if (more) {
            a4 = *(const float4*)(Ag + k0 + 8);
            b4 = *(const float4*)(Wg + k0 + 8);
        }

        #pragma unroll
        for (int kk = 0; kk < 8; kk++) {
            float4 x0 = *(const float4*)&As[buf][kk][trow];
            float4 x1 = *(const float4*)&As[buf][kk][trow + 4];
            float4 y0 = *(const float4*)&Bs[buf][kk][tcol];
            float4 y1 = *(const float4*)&Bs[buf][kk][tcol + 4];
            float ar[8] = {x0.x,x0.y,x0.z,x0.w,x1.x,x1.y,x1.z,x1.w};
            float br[8] = {y0.x,y0.y,y0.z,y0.w,y1.x,y1.y,y1.z,y1.w};
            #pragma unroll
            for (int i = 0; i < 8; i++)
                #pragma unroll
                for (int j = 0; j < 8; j++)
                    acc[i][j] = fmaf(ar[i], br[j], acc[i][j]);
        }

        if (more) {
            int nb = buf ^ 1;
            As[nb][lk+0][lrow] = a4.x; As[nb][lk+1][lrow] = a4.y;
            As[nb][lk+2][lrow] = a4.z; As[nb][lk+3][lrow] = a4.w;
            Bs[nb][lk+0][lrow] = b4.x; Bs[nb][lk+1][lrow] = b4.y;
            Bs[nb][lk+2][lrow] = b4.z; Bs[nb][lk+3][lrow] = b4.w;
        }
        __syncthreads();
        buf ^= 1;
    }

    float bv[8];
    if (HASBIAS) {
        #pragma unroll
        for (int j = 0; j < 8; j++) bv[j] = bias[bcol + tcol + j];
    }
    #pragma unroll
    for (int i = 0; i < 8; i++) {
        float* Cp = C + (brow + trow + i) * DMODEL + bcol + tcol;
        float4 v0 = make_float4(acc[i][0], acc[i][1], acc[i][2], acc[i][3]);
        float4 v1 = make_float4(acc[i][4], acc[i][5], acc[i][6], acc[i][7]);
        if (HASBIAS) {
            v0.x += bv[0]; v0.y += bv[1]; v0.z += bv[2]; v0.w += bv[3];
            v1.x += bv[4]; v1.y += bv[5]; v1.z += bv[6]; v1.w += bv[7];
        }
        *(float4*)Cp       = v0;
        *(float4*)(Cp + 4) = v1;
    }
}

extern "C" __global__ void __launch_bounds__(256, 2)
qkv_gemm_kernel(const float* __restrict__ X,
                const float* __restrict__ Wq,
                const float* __restrict__ Wk,
                const float* __restrict__ Wv)
{
    const float* W;
    float* C;
    if (blockIdx.z == 0)      { W = Wq; C = g_q; }
    else if (blockIdx.z == 1) { W = Wk; C = g_k; }
    else                      { W = Wv; C = g_v; }
    sgemm_body<false>(X, W, C, nullptr);
}

extern "C" __global__ void __launch_bounds__(256, 2)
out_gemm_kernel(const float* __restrict__ Wo,
                const float* __restrict__ bo,
                float* __restrict__ out)
{
    sgemm_body<true>(g_ao, Wo, out, bo);
}

// ============================================================
// RoPE: cos/sin table in double (phase accuracy), then apply.
// ============================================================
extern "C" __global__ void __launch_bounds__(256)
rope_table_kernel()
{
    int idx = blockIdx.x * 256 + threadIdx.x;   // < 2048*32
    int t = idx >> 5;
    int d = idx & 31;
    double freq = pow(10000.0, -(double)d / 32.0);
    double ang  = (double)t * freq;
    double sd, cd;
    sincos(ang, &sd, &cd);
    g_cos[idx] = (float)cd;
    g_sin[idx] = (float)sd;
}

extern "C" __global__ void __launch_bounds__(256)
rope_apply_kernel()
{
    int idx = blockIdx.x * 256 + threadIdx.x;   // < 4096*16*32
    int d  = idx & 31;
    int h  = (idx >> 5) & 15;
    int bt = idx >> 9;
    int t  = bt & (TDIM - 1);

    float c = g_cos[t * 32 + d];
    float s = g_sin[t * 32 + d];

    int base = bt * DMODEL + h * DH + d;

    float a = g_q[base], b = g_q[base + 32];
    g_q[base]      = a * c - b * s;
    g_q[base + 32] = b * c + a * s;

    a = g_k[base]; b = g_k[base + 32];
    g_k[base]      = a * c - b * s;
    g_k[base + 32] = b * c + a * s;
}

// ============================================================
// Sliding-window attention, register-tiled.
// 64-query tile, key window of 192 rows, 256 threads.
// Phase 1: scores as 64x192 GEMM, 4x12 per-thread tile.
// Phase 2: softmax, 4 threads per row + shfl reduce.
// Phase 3: PV as 64x64 GEMM over 192 keys, 4x4 per-thread tile.
// smem: Q[64][65] K[192][65] V[192][65] S[64][193]  (165888 B)
// ============================================================
#define ATTN_THREADS 256
#define ATTN_SMEM_FLOATS (64*65 + 192*65 + 192*65 + 64*193)
#define ATTN_SMEM_BYTES  (ATTN_SMEM_FLOATS * 4)

extern "C" __global__ void __launch_bounds__(ATTN_THREADS)
attn_kernel()
{
    extern __shared__ float sm[];
    float* Qs = sm;                    // [64][65]
    float* Ks = Qs + 64 * 65;          // [192][65]
    float* Vs = Ks + 192 * 65;         // [192][65]
    float* Ss = Vs + 192 * 65;         // [64][193]

    const int tid = threadIdx.x;
    const int q0  = blockIdx.x * 64;
    const int h   = blockIdx.y;
    const int b   = blockIdx.z;

    const int k0 = max(0, q0 - (WIN - 1));
    const int nk = q0 + 64 - k0;       // <= 192

    const float* Qg = g_q + (b * TDIM + q0) * DMODEL + h * DH;
    const float* Kg = g_k + (b * TDIM + k0) * DMODEL + h * DH;
    const float* Vg = g_v + (b * TDIM + k0) * DMODEL + h * DH;

    // loads (float4 from gmem, scalar stores into padded smem)
    for (int idx = tid; idx < 64 * 16; idx += ATTN_THREADS) {
        int i = idx >> 4, c = (idx & 15) * 4;
        float4 v = *(const float4*)(Qg + i * DMODEL + c);
        float* p = Qs + i * 65 + c;
        p[0] = v.x; p[1] = v.y; p[2] = v.z; p[3] = v.w;
    }
    for (int idx = tid; idx < nk * 16; idx += ATTN_THREADS) {
        int j = idx >> 4, c = (idx & 15) * 4;
        float4 vk = *(const float4*)(Kg + j * DMODEL + c);
        float4 vv = *(const float4*)(Vg + j * DMODEL + c);
        float* pk = Ks + j * 65 + c;
        float* pv = Vs + j * 65 + c;
        pk[0] = vk.x; pk[1] = vk.y; pk[2] = vk.z; pk[3] = vk.w;
        pv[0] = vv.x; pv[1] = vv.y; pv[2] = vv.z; pv[3] = vv.w;
    }
    // zero V tail so dense PV over 192 keys stays clean
    for (int idx = nk * 64 + tid; idx < 192 * 64; idx += ATTN_THREADS) {
        int j = idx >> 6, d = idx & 63;
        Vs[j * 65 + d] = 0.0f;
    }
    __syncthreads();

    // ---- Phase 1: scores, 4 queries x 12 keys per thread ----
    {
        const int ty = tid >> 4;       // 0..15 -> queries ty*4 .. +3
        const int tx = tid & 15;       // keys tx + 16*u, u=0..11
        float acc[4][12];
        #pragma unroll
        for (int i = 0; i < 4; i++)
            #pragma unroll
            for (int u = 0; u < 12; u++) acc[i][u] = 0.0f;

        const float* qb = Qs + (ty * 4) * 65;
        const float* kb = Ks + tx * 65;

        #pragma unroll 4
        for (int d = 0; d < DH; d++) {
            float qv[4];
            #pragma unroll
            for (int i = 0; i < 4; i++) qv[i] = qb[i * 65 + d];
            float kv[12];
            #pragma unroll
            for (int u = 0; u < 12; u++) kv[u] = kb[u * 16 * 65 + d];
            #pragma unroll
            for (int i = 0; i < 4; i++)
                #pragma unroll
                for (int u = 0; u < 12; u++)
                    acc[i][u] = fmaf(qv[i], kv[u], acc[i][u]);
        }

        #pragma unroll
        for (int i = 0; i < 4; i++) {
            int iq = q0 + ty * 4 + i;
            #pragma unroll
            for (int u = 0; u < 12; u++) {
                int j  = tx + 16 * u;
                int jg = k0 + j;
                bool valid = (j < nk) && (jg <= iq) && (jg >= iq - (WIN - 1));
                Ss[(ty * 4 + i) * 193 + j] = valid ? acc[i][u] * 0.125f : -INFINITY;
            }
        }
    }
    __syncthreads();

    // ---- Phase 2: softmax, 4 threads per row ----
    {
        const int row = tid >> 2;
        const int g   = tid & 3;
        float* sp = Ss + row * 193;
        float m = -INFINITY;
        for (int j = g; j < 192; j += 4) m = fmaxf(m, sp[j]);
        m = fmaxf(m, __shfl_xor_sync(0xffffffffu, m, 1));
        m = fmaxf(m, __shfl_xor_sync(0xffffffffu, m, 2));
        float sum = 0.0f;
        for (int j = g; j < 192; j += 4) {
            float e = __expf(sp[j] - m);
            sp[j] = e;
            sum += e;
        }
        sum += __shfl_xor_sync(0xffffffffu, sum, 1);
        sum += __shfl_xor_sync(0xffffffffu, sum, 2);
        float inv = 1.0f / sum;
        for (int j = g; j < 192; j += 4) sp[j] *= inv;
    }
    __syncthreads();

    // ---- Phase 3: O = P @ V, 4 rows x 4 cols per thread ----
    {
        const int ty = tid >> 4;       // rows ty*4 .. +3
        const int tx = tid & 15;       // cols tx + 16*dd, dd=0..3
        float acc[4][4];
        #pragma unroll
        for (int i = 0; i < 4; i++)
            #pragma unroll
            for (int d = 0; d < 4; d++) acc[i][d] = 0.0f;

        const float* pb = Ss + (ty * 4) * 193;
        const float* vb = Vs + tx;

        #pragma unroll 4
        for (int k = 0; k < 192; k++) {
            float pv[4];
            #pragma unroll
            for (int i = 0; i < 4; i++) pv[i] = pb[i * 193 + k];
            float vv[4];
            #pragma unroll
            for (int d = 0; d < 4; d++) vv[d] = vb[k * 65 + 16 * d];
            #pragma unroll
            for (int i = 0; i < 4; i++)
                #pragma unroll
                for (int d = 0; d < 4; d++)
                    acc[i][d] = fmaf(pv[i], vv[d], acc[i][d]);
        }

        float* Og = g_ao + (b * TDIM + q0) * DMODEL + h * DH;
        #pragma unroll
        for (int i = 0; i < 4; i++)
            #pragma unroll
            for (int d = 0; d < 4; d++)
                Og[(ty * 4 + i) * DMODEL + tx + 16 * d] = acc[i][d];
    }
}

// ============================================================
// launch
// ============================================================
extern "C" void kernel_launch(void* const* d_in, const int* in_sizes, int n_in,
                              void* d_out, int out_size)
{
    const float* X  = (const float*)d_in[0];
    const float* Wq = (const float*)d_in[1];
    const float* Wk = (const float*)d_in[2];
    const float* Wv = (const float*)d_in[3];
    const float* Wo = (const float*)d_in[4];
    const float* bo = (const float*)d_in[5];
    float* out = (float*)d_out;

    cudaFuncSetAttribute(attn_kernel,
                         cudaFuncAttributeMaxDynamicSharedMemorySize,
                         ATTN_SMEM_BYTES);

    rope_table_kernel<<<(TDIM * 32) / 256, 256>>>();
    qkv_gemm_kernel<<<dim3(DMODEL / 128, MTOT / 128, 3), 256>>>(X, Wq, Wk, Wv);
    rope_apply_kernel<<<(MTOT * NH * 32) / 256, 256>>>();
    attn_kernel<<<dim3(TDIM / 64, NH, BDIM), ATTN_THREADS, ATTN_SMEM_BYTES>>>();
    out_gemm_kernel<<<dim3(DMODEL / 128, MTOT / 128, 1), 256>>>(Wo, bo, out);
}

// round 8
// speedup vs baseline: 2.7677x; 2.7677x over previous
#include <cuda_runtime.h>
#include <cuda_bf16.h>
#include <math.h>
#include <stdint.h>

#define TDIM   2048
#define BDIM   2
#define DMODEL 1024
#define NH     16
#define DH     64
#define WIN    128
#define MTOT   (BDIM*TDIM)          // 4096 rows

// -------- scratch (device globals: allocation-free) --------
__device__ float g_q [MTOT*DMODEL];
__device__ float g_k [MTOT*DMODEL];
__device__ float g_v [MTOT*DMODEL];
__device__ float g_cos[TDIM*32];
__device__ float g_sin[TDIM*32];

// bf16 split operands
__device__ __nv_bfloat16 g_xhi [MTOT*DMODEL];
__device__ __nv_bfloat16 g_xlo [MTOT*DMODEL];
__device__ __nv_bfloat16 g_whi [4*DMODEL*DMODEL];   // q,k,v,o
__device__ __nv_bfloat16 g_wlo [4*DMODEL*DMODEL];
__device__ __nv_bfloat16 g_aohi[MTOT*DMODEL];
__device__ __nv_bfloat16 g_aolo[MTOT*DMODEL];

// ============================================================
// fp32 -> (hi, lo) bf16 split conversion
// ============================================================
extern "C" __global__ void __launch_bounds__(256)
cvt_kernel(const float* __restrict__ src,
           __nv_bfloat16* __restrict__ hi,
           __nv_bfloat16* __restrict__ lo, int n)
{
    int i = blockIdx.x * 256 + threadIdx.x;
    if (i < n) {
        float x = src[i];
        __nv_bfloat16 h = __float2bfloat16(x);
        float r = x - __bfloat162float(h);
        hi[i] = h;
        lo[i] = __float2bfloat16(r);
    }
}

// ============================================================
// Split-bf16 GEMM on tensor cores (mma.sync m16n8k16):
//   C[m][n] = sum_k A[m][k]*W[n][k]  via Ahi*Bhi + Ahi*Blo + Alo*Bhi
// CTA 128x128, K-chunk 32, 512 threads (16 warps, 4x4), warp 32x32.
// ============================================================
#define GPAD 40   // halves per smem row (20 words -> conflict-free frags)

__device__ __forceinline__ void mma16816(
    float& c0, float& c1, float& c2, float& c3,
    uint32_t a0, uint32_t a1, uint32_t a2, uint32_t a3,
    uint32_t b0, uint32_t b1)
{
    asm volatile(
        "mma.sync.aligned.m16n8k16.row.col.f32.bf16.bf16.f32 "
        "{%0,%1,%2,%3}, {%4,%5,%6,%7}, {%8,%9}, {%0,%1,%2,%3};"
        : "+f"(c0), "+f"(c1), "+f"(c2), "+f"(c3)
        : "r"(a0), "r"(a1), "r"(a2), "r"(a3), "r"(b0), "r"(b1));
}

template<bool HASBIAS>
__device__ __forceinline__ void gemm_split_body(
    const __nv_bfloat16* __restrict__ Ahi, const __nv_bfloat16* __restrict__ Alo,
    const __nv_bfloat16* __restrict__ Bhi, const __nv_bfloat16* __restrict__ Blo,
    float* __restrict__ C, const float* __restrict__ bias)
{
    __shared__ __align__(16) __nv_bfloat16 sAh[128*GPAD];
    __shared__ __align__(16) __nv_bfloat16 sAl[128*GPAD];
    __shared__ __align__(16) __nv_bfloat16 sBh[128*GPAD];
    __shared__ __align__(16) __nv_bfloat16 sBl[128*GPAD];

    const int tid  = threadIdx.x;
    const int bm0  = blockIdx.y * 128;
    const int bn0  = blockIdx.x * 128;

    // global-load mapping: each thread one uint4 (8 halves) per array
    const int gr = tid >> 2;             // 0..127
    const int gc = (tid & 3) * 8;        // 0,8,16,24

    const uint4* pAh = (const uint4*)(Ahi + (bm0 + gr) * DMODEL + gc);
    const uint4* pAl = (const uint4*)(Alo + (bm0 + gr) * DMODEL + gc);
    const uint4* pBh = (const uint4*)(Bhi + (bn0 + gr) * DMODEL + gc);
    const uint4* pBl = (const uint4*)(Blo + (bn0 + gr) * DMODEL + gc);

    uint4* sAhp = (uint4*)(sAh + gr * GPAD + gc);
    uint4* sAlp = (uint4*)(sAl + gr * GPAD + gc);
    uint4* sBhp = (uint4*)(sBh + gr * GPAD + gc);
    uint4* sBlp = (uint4*)(sBl + gr * GPAD + gc);

    // warp tiling: 4x4 warps, each 32x32
    const int warp = tid >> 5;
    const int lane = tid & 31;
    const int wm   = (warp >> 2) * 32;   // 0,32,64,96
    const int wn   = (warp & 3) * 32;
    const int grp  = lane >> 2;          // 0..7
    const int tg   = lane & 3;           // 0..3

    float acc[2][4][4];
    #pragma unroll
    for (int mi = 0; mi < 2; mi++)
        #pragma unroll
        for (int ni = 0; ni < 4; ni++)
            #pragma unroll
            for (int c = 0; c < 4; c++) acc[mi][ni][c] = 0.0f;

    uint4 ra = pAh[0], rb = pAl[0], rc = pBh[0], rd = pBl[0];

    const int NITER = DMODEL / 32;       // 32 (uint4 stride per iter = 4)
    for (int kt = 0; kt < NITER; kt++) {
        *sAhp = ra; *sAlp = rb; *sBhp = rc; *sBlp = rd;
        __syncthreads();

        if (kt + 1 < NITER) {
            ra = pAh[(kt + 1) * 4];
            rb = pAl[(kt + 1) * 4];
            rc = pBh[(kt + 1) * 4];
            rd = pBl[(kt + 1) * 4];
        }

        #pragma unroll
        for (int kk = 0; kk < 32; kk += 16) {
            // fragment smem offsets (halves); all 32-bit aligned (even idx)
            const int arow0 = (wm + grp) * GPAD + kk + tg * 2;
            const int arow1 = (wm + 8 + grp) * GPAD + kk + tg * 2;
            const int arow2 = (wm + 16 + grp) * GPAD + kk + tg * 2;
            const int arow3 = (wm + 24 + grp) * GPAD + kk + tg * 2;

            uint32_t ah[2][4], al[2][4], bh[4][2], bl[4][2];
            // A hi frags: mi=0 rows wm..wm+15, mi=1 rows wm+16..wm+31
            ah[0][0] = *(const uint32_t*)(sAh + arow0);
            ah[0][1] = *(const uint32_t*)(sAh + arow1);
            ah[0][2] = *(const uint32_t*)(sAh + arow0 + 8);
            ah[0][3] = *(const uint32_t*)(sAh + arow1 + 8);
            ah[1][0] = *(const uint32_t*)(sAh + arow2);
            ah[1][1] = *(const uint32_t*)(sAh + arow3);
            ah[1][2] = *(const uint32_t*)(sAh + arow2 + 8);
            ah[1][3] = *(const uint32_t*)(sAh + arow3 + 8);
            al[0][0] = *(const uint32_t*)(sAl + arow0);
            al[0][1] = *(const uint32_t*)(sAl + arow1);
            al[0][2] = *(const uint32_t*)(sAl + arow0 + 8);
            al[0][3] = *(const uint32_t*)(sAl + arow1 + 8);
            al[1][0] = *(const uint32_t*)(sAl + arow2);
            al[1][1] = *(const uint32_t*)(sAl + arow3);
            al[1][2] = *(const uint32_t*)(sAl + arow2 + 8);
            al[1][3] = *(const uint32_t*)(sAl + arow3 + 8);
            #pragma unroll
            for (int ni = 0; ni < 4; ni++) {
                const int bcol = (wn + ni * 8 + grp) * GPAD + kk + tg * 2;
                bh[ni][0] = *(const uint32_t*)(sBh + bcol);
                bh[ni][1] = *(const uint32_t*)(sBh + bcol + 8);
                bl[ni][0] = *(const uint32_t*)(sBl + bcol);
                bl[ni][1] = *(const uint32_t*)(sBl + bcol + 8);
            }

            #pragma unroll
            for (int mi = 0; mi < 2; mi++)
                #pragma unroll
                for (int ni = 0; ni < 4; ni++) {
                    float* cc = acc[mi][ni];
                    // hi*hi
                    mma16816(cc[0], cc[1], cc[2], cc[3],
                             ah[mi][0], ah[mi][1], ah[mi][2], ah[mi][3],
                             bh[ni][0], bh[ni][1]);
                    // lo*hi
                    mma16816(cc[0], cc[1], cc[2], cc[3],
                             al[mi][0], al[mi][1], al[mi][2], al[mi][3],
                             bh[ni][0], bh[ni][1]);
                    // hi*lo
                    mma16816(cc[0], cc[1], cc[2], cc[3],
                             ah[mi][0], ah[mi][1], ah[mi][2], ah[mi][3],
                             bl[ni][0], bl[ni][1]);
                }
        }
        __syncthreads();
    }

    // store: frag (mi, ni): rows bm0+wm+mi*16+grp (+8), cols bn0+wn+ni*8+tg*2 (+1)
    #pragma unroll
    for (int mi = 0; mi < 2; mi++)
        #pragma unroll
        for (int ni = 0; ni < 4; ni++) {
            int row = bm0 + wm + mi * 16 + grp;
            int col = bn0 + wn + ni * 8 + tg * 2;
            float b0 = 0.f, b1 = 0.f;
            if (HASBIAS) { b0 = bias[col]; b1 = bias[col + 1]; }
            float2 v0 = make_float2(acc[mi][ni][0] + b0, acc[mi][ni][1] + b1);
            float2 v1 = make_float2(acc[mi][ni][2] + b0, acc[mi][ni][3] + b1);
            *(float2*)(C + row * DMODEL + col)       = v0;
            *(float2*)(C + (row + 8) * DMODEL + col) = v1;
        }
}

extern "C" __global__ void __launch_bounds__(512)
qkv_mma_kernel()
{
    const __nv_bfloat16* Wh = g_whi + blockIdx.z * DMODEL * DMODEL;
    const __nv_bfloat16* Wl = g_wlo + blockIdx.z * DMODEL * DMODEL;
    float* C = (blockIdx.z == 0) ? g_q : (blockIdx.z == 1) ? g_k : g_v;
    gemm_split_body<false>(g_xhi, g_xlo, Wh, Wl, C, nullptr);
}

extern "C" __global__ void __launch_bounds__(512)
out_mma_kernel(const float* __restrict__ bo, float* __restrict__ out)
{
    gemm_split_body<true>(g_aohi, g_aolo,
                          g_whi + 3 * DMODEL * DMODEL,
                          g_wlo + 3 * DMODEL * DMODEL, out, bo);
}

// ============================================================
// RoPE: cos/sin table in double (phase accuracy), then apply.
// ============================================================
extern "C" __global__ void __launch_bounds__(256)
rope_table_kernel()
{
    int idx = blockIdx.x * 256 + threadIdx.x;   // < 2048*32
    int t = idx >> 5;
    int d = idx & 31;
    double freq = pow(10000.0, -(double)d / 32.0);
    double ang  = (double)t * freq;
    double sd, cd;
    sincos(ang, &sd, &cd);
    g_cos[idx] = (float)cd;
    g_sin[idx] = (float)sd;
}

extern "C" __global__ void __launch_bounds__(256)
rope_apply_kernel()
{
    int idx = blockIdx.x * 256 + threadIdx.x;   // < 4096*16*32
    int d  = idx & 31;
    int h  = (idx >> 5) & 15;
    int bt = idx >> 9;
    int t  = bt & (TDIM - 1);

    float c = g_cos[t * 32 + d];
    float s = g_sin[t * 32 + d];

    int base = bt * DMODEL + h * DH + d;

    float a = g_q[base], b = g_q[base + 32];
    g_q[base]      = a * c - b * s;
    g_q[base + 32] = b * c + a * s;

    a = g_k[base]; b = g_k[base + 32];
    g_k[base]      = a * c - b * s;
    g_k[base + 32] = b * c + a * s;
}

// ============================================================
// Sliding-window attention, register-tiled (round-5 version),
// now emitting split-bf16 output directly.
// ============================================================
#define ATTN_THREADS 256
#define ATTN_SMEM_FLOATS (64*65 + 192*65 + 192*65 + 64*193)
#define ATTN_SMEM_BYTES  (ATTN_SMEM_FLOATS * 4)

extern "C" __global__ void __launch_bounds__(ATTN_THREADS)
attn_kernel()
{
    extern __shared__ float sm[];
    float* Qs = sm;                    // [64][65]
    float* Ks = Qs + 64 * 65;          // [192][65]
    float* Vs = Ks + 192 * 65;         // [192][65]
    float* Ss = Vs + 192 * 65;         // [64][193]

    const int tid = threadIdx.x;
    const int q0  = blockIdx.x * 64;
    const int h   = blockIdx.y;
    const int b   = blockIdx.z;

    const int k0 = max(0, q0 - (WIN - 1));
    const int nk = q0 + 64 - k0;       // <= 192

    const float* Qg = g_q + (b * TDIM + q0) * DMODEL + h * DH;
    const float* Kg = g_k + (b * TDIM + k0) * DMODEL + h * DH;
    const float* Vg = g_v + (b * TDIM + k0) * DMODEL + h * DH;

    for (int idx = tid; idx < 64 * 16; idx += ATTN_THREADS) {
        int i = idx >> 4, c = (idx & 15) * 4;
        float4 v = *(const float4*)(Qg + i * DMODEL + c);
        float* p = Qs + i * 65 + c;
        p[0] = v.x; p[1] = v.y; p[2] = v.z; p[3] = v.w;
    }
    for (int idx = tid; idx < nk * 16; idx += ATTN_THREADS) {
        int j = idx >> 4, c = (idx & 15) * 4;
        float4 vk = *(const float4*)(Kg + j * DMODEL + c);
        float4 vv = *(const float4*)(Vg + j * DMODEL + c);
        float* pk = Ks + j * 65 + c;
        float* pv = Vs + j * 65 + c;
        pk[0] = vk.x; pk[1] = vk.y; pk[2] = vk.z; pk[3] = vk.w;
        pv[0] = vv.x; pv[1] = vv.y; pv[2] = vv.z; pv[3] = vv.w;
    }
    for (int idx = nk * 64 + tid; idx < 192 * 64; idx += ATTN_THREADS) {
        int j = idx >> 6, d = idx & 63;
        Vs[j * 65 + d] = 0.0f;
    }
    __syncthreads();

    // ---- Phase 1: scores, 4 queries x 12 keys per thread ----
    {
        const int ty = tid >> 4;
        const int tx = tid & 15;
        float acc[4][12];
        #pragma unroll
        for (int i = 0; i < 4; i++)
            #pragma unroll
            for (int u = 0; u < 12; u++) acc[i][u] = 0.0f;

        const float* qb = Qs + (ty * 4) * 65;
        const float* kb = Ks + tx * 65;

        #pragma unroll 4
        for (int d = 0; d < DH; d++) {
            float qv[4];
            #pragma unroll
            for (int i = 0; i < 4; i++) qv[i] = qb[i * 65 + d];
            float kv[12];
            #pragma unroll
            for (int u = 0; u < 12; u++) kv[u] = kb[u * 16 * 65 + d];
            #pragma unroll
            for (int i = 0; i < 4; i++)
                #pragma unroll
                for (int u = 0; u < 12; u++)
                    acc[i][u] = fmaf(qv[i], kv[u], acc[i][u]);
        }

        #pragma unroll
        for (int i = 0; i < 4; i++) {
            int iq = q0 + ty * 4 + i;
            #pragma unroll
            for (int u = 0; u < 12; u++) {
                int j  = tx + 16 * u;
                int jg = k0 + j;
                bool valid = (j < nk) && (jg <= iq) && (jg >= iq - (WIN - 1));
                Ss[(ty * 4 + i) * 193 + j] = valid ? acc[i][u] * 0.125f : -INFINITY;
            }
        }
    }
    __syncthreads();

    // ---- Phase 2: softmax, 4 threads per row ----
    {
        const int row = tid >> 2;
        const int g   = tid & 3;
        float* sp = Ss + row * 193;
        float m = -INFINITY;
        for (int j = g; j < 192; j += 4) m = fmaxf(m, sp[j]);
        m = fmaxf(m, __shfl_xor_sync(0xffffffffu, m, 1));
        m = fmaxf(m, __shfl_xor_sync(0xffffffffu, m, 2));
        float sum = 0.0f;
        for (int j = g; j < 192; j += 4) {
            float e = __expf(sp[j] - m);
            sp[j] = e;
            sum += e;
        }
        sum += __shfl_xor_sync(0xffffffffu, sum, 1);
        sum += __shfl_xor_sync(0xffffffffu, sum, 2);
        float inv = 1.0f / sum;
        for (int j = g; j < 192; j += 4) sp[j] *= inv;
    }
    __syncthreads();

    // ---- Phase 3: O = P @ V, 4x4 per thread; write split bf16 ----
    {
        const int ty = tid >> 4;
        const int tx = tid & 15;
        float acc[4][4];
        #pragma unroll
        for (int i = 0; i < 4; i++)
            #pragma unroll
            for (int d = 0; d < 4; d++) acc[i][d] = 0.0f;

        const float* pb = Ss + (ty * 4) * 193;
        const float* vb = Vs + tx;

        #pragma unroll 4
        for (int k = 0; k < 192; k++) {
            float pv[4];
            #pragma unroll
            for (int i = 0; i < 4; i++) pv[i] = pb[i * 193 + k];
            float vv[4];
            #pragma unroll
            for (int d = 0; d < 4; d++) vv[d] = vb[k * 65 + 16 * d];
            #pragma unroll
            for (int i = 0; i < 4; i++)
                #pragma unroll
                for (int d = 0; d < 4; d++)
                    acc[i][d] = fmaf(pv[i], vv[d], acc[i][d]);
        }

        long base = (long)(b * TDIM + q0) * DMODEL + h * DH;
        #pragma unroll
        for (int i = 0; i < 4; i++)
            #pragma unroll
            for (int d = 0; d < 4; d++) {
                float v = acc[i][d];
                __nv_bfloat16 hh = __float2bfloat16(v);
                float r = v - __bfloat162float(hh);
                long off = base + (long)(ty * 4 + i) * DMODEL + tx + 16 * d;
                g_aohi[off] = hh;
                g_aolo[off] = __float2bfloat16(r);
            }
    }
}

// ============================================================
// launch
// ============================================================
extern "C" void kernel_launch(void* const* d_in, const int* in_sizes, int n_in,
                              void* d_out, int out_size)
{
    const float* X  = (const float*)d_in[0];
    const float* Wq = (const float*)d_in[1];
    const float* Wk = (const float*)d_in[2];
    const float* Wv = (const float*)d_in[3];
    const float* Wo = (const float*)d_in[4];
    const float* bo = (const float*)d_in[5];
    float* out = (float*)d_out;

    cudaFuncSetAttribute(attn_kernel,
                         cudaFuncAttributeMaxDynamicSharedMemorySize,
                         ATTN_SMEM_BYTES);

    // resolve device-global scratch addresses for cvt targets
    __nv_bfloat16 *xhi, *xlo, *whi, *wlo;
    cudaGetSymbolAddress((void**)&xhi, g_xhi);
    cudaGetSymbolAddress((void**)&xlo, g_xlo);
    cudaGetSymbolAddress((void**)&whi, g_whi);
    cudaGetSymbolAddress((void**)&wlo, g_wlo);

    const int NW = DMODEL * DMODEL;          // 1M
    rope_table_kernel<<<(TDIM * 32) / 256, 256>>>();
    cvt_kernel<<<(MTOT * DMODEL) / 256, 256>>>(X, xhi, xlo, MTOT * DMODEL);
    cvt_kernel<<<NW / 256, 256>>>(Wq, whi + 0 * NW, wlo + 0 * NW, NW);
    cvt_kernel<<<NW / 256, 256>>>(Wk, whi + 1 * NW, wlo + 1 * NW, NW);
    cvt_kernel<<<NW / 256, 256>>>(Wv, whi + 2 * NW, wlo + 2 * NW, NW);
    cvt_kernel<<<NW / 256, 256>>>(Wo, whi + 3 * NW, wlo + 3 * NW, NW);

    qkv_mma_kernel<<<dim3(DMODEL / 128, MTOT / 128, 3), 512>>>();
    rope_apply_kernel<<<(MTOT * NH * 32) / 256, 256>>>();
    attn_kernel<<<dim3(TDIM / 64, NH, BDIM), ATTN_THREADS, ATTN_SMEM_BYTES>>>();
    out_mma_kernel<<<dim3(DMODEL / 128, MTOT / 128, 1), 512>>>(bo, out);
}

// round 10
// speedup vs baseline: 2.9127x; 1.0524x over previous
#include <cuda_runtime.h>
#include <cuda_bf16.h>
#include <math.h>
#include <stdint.h>

#define TDIM   2048
#define BDIM   2
#define DMODEL 1024
#define NH     16
#define DH     64
#define WIN    128
#define MTOT   (BDIM*TDIM)          // 4096 rows

// -------- scratch (device globals: allocation-free) --------
__device__ float g_q [MTOT*DMODEL];
__device__ float g_k [MTOT*DMODEL];
__device__ float g_v [MTOT*DMODEL];
__device__ float g_cos[TDIM*32];
__device__ float g_sin[TDIM*32];

// bf16 split operands
__device__ __nv_bfloat16 g_xhi [MTOT*DMODEL];
__device__ __nv_bfloat16 g_xlo [MTOT*DMODEL];
__device__ __nv_bfloat16 g_whi [4*DMODEL*DMODEL];   // q,k,v,o
__device__ __nv_bfloat16 g_wlo [4*DMODEL*DMODEL];
__device__ __nv_bfloat16 g_aohi[MTOT*DMODEL];
__device__ __nv_bfloat16 g_aolo[MTOT*DMODEL];

// ============================================================
// fp32 -> (hi, lo) bf16 split, vectorized, all 5 tensors in one
// launch (grid.y selects tensor).
// ============================================================
extern "C" __global__ void __launch_bounds__(256)
cvt4_kernel(const float* __restrict__ X,
            const float* __restrict__ W0, const float* __restrict__ W1,
            const float* __restrict__ W2, const float* __restrict__ W3,
            __nv_bfloat16* __restrict__ xhi, __nv_bfloat16* __restrict__ xlo,
            __nv_bfloat16* __restrict__ whi, __nv_bfloat16* __restrict__ wlo)
{
    const int NW = DMODEL * DMODEL;
    const float* src;
    __nv_bfloat16 *hi, *lo;
    int n;
    int y = blockIdx.y;
    if (y == 0) { src = X;  hi = xhi; lo = xlo; n = MTOT * DMODEL; }
    else {
        src = (y == 1) ? W0 : (y == 2) ? W1 : (y == 3) ? W2 : W3;
        hi = whi + (y - 1) * NW;
        lo = wlo + (y - 1) * NW;
        n = NW;
    }
    int i = (blockIdx.x * 256 + threadIdx.x) * 4;
    if (i >= n) return;
    float4 v = *(const float4*)(src + i);
    __nv_bfloat16 h0 = __float2bfloat16(v.x);
    __nv_bfloat16 h1 = __float2bfloat16(v.y);
    __nv_bfloat16 h2 = __float2bfloat16(v.z);
    __nv_bfloat16 h3 = __float2bfloat16(v.w);
    __nv_bfloat16 l0 = __float2bfloat16(v.x - __bfloat162float(h0));
    __nv_bfloat16 l1 = __float2bfloat16(v.y - __bfloat162float(h1));
    __nv_bfloat16 l2 = __float2bfloat16(v.z - __bfloat162float(h2));
    __nv_bfloat16 l3 = __float2bfloat16(v.w - __bfloat162float(h3));
    ushort4 ph = make_ushort4(*(unsigned short*)&h0, *(unsigned short*)&h1,
                              *(unsigned short*)&h2, *(unsigned short*)&h3);
    ushort4 pl = make_ushort4(*(unsigned short*)&l0, *(unsigned short*)&l1,
                              *(unsigned short*)&l2, *(unsigned short*)&l3);
    *(ushort4*)(hi + i) = ph;
    *(ushort4*)(lo + i) = pl;
}

// ============================================================
// Split-bf16 GEMM on tensor cores (mma.sync m16n8k16):
//   C[m][n] = sum_k A[m][k]*W[n][k]  via Ahi*Bhi + Ahi*Blo + Alo*Bhi
// CTA 128x256, K-chunk 32, 512 threads (16 warps 4x4), warp 32x64.
// Dynamic smem: A(hi,lo) 128x40 + B(hi,lo) 256x40 halves = 60KB.
// ============================================================
#define GPAD 40   // halves per smem row (20 words -> conflict-free frags)
#define GEMM_SMEM_BYTES ((2*128*GPAD + 2*256*GPAD) * 2)

__device__ __forceinline__ void mma16816(
    float& c0, float& c1, float& c2, float& c3,
    uint32_t a0, uint32_t a1, uint32_t a2, uint32_t a3,
    uint32_t b0, uint32_t b1)
{
    asm volatile(
        "mma.sync.aligned.m16n8k16.row.col.f32.bf16.bf16.f32 "
        "{%0,%1,%2,%3}, {%4,%5,%6,%7}, {%8,%9}, {%0,%1,%2,%3};"
        : "+f"(c0), "+f"(c1), "+f"(c2), "+f"(c3)
        : "r"(a0), "r"(a1), "r"(a2), "r"(a3), "r"(b0), "r"(b1));
}

template<bool HASBIAS>
__device__ __forceinline__ void gemm_split_body(
    const __nv_bfloat16* __restrict__ Ahi, const __nv_bfloat16* __restrict__ Alo,
    const __nv_bfloat16* __restrict__ Bhi, const __nv_bfloat16* __restrict__ Blo,
    float* __restrict__ C, const float* __restrict__ bias)
{
    extern __shared__ __align__(16) __nv_bfloat16 gsm[];
    __nv_bfloat16* sAh = gsm;                    // 128*GPAD
    __nv_bfloat16* sAl = sAh + 128 * GPAD;
    __nv_bfloat16* sBh = sAl + 128 * GPAD;       // 256*GPAD
    __nv_bfloat16* sBl = sBh + 256 * GPAD;

    const int tid = threadIdx.x;
    const int bm0 = blockIdx.y * 128;
    const int bn0 = blockIdx.x * 256;

    // global-load mapping
    const int ar = tid >> 2;             // 0..127
    const int ac = (tid & 3) * 8;        // 0,8,16,24
    const int br = tid >> 1;             // 0..255
    const int bc = (tid & 1) * 16;       // 0,16

    const uint4* pAh = (const uint4*)(Ahi + (bm0 + ar) * DMODEL + ac);
    const uint4* pAl = (const uint4*)(Alo + (bm0 + ar) * DMODEL + ac);
    const uint4* pBh = (const uint4*)(Bhi + (bn0 + br) * DMODEL + bc);
    const uint4* pBl = (const uint4*)(Blo + (bn0 + br) * DMODEL + bc);

    uint4* sAhp = (uint4*)(sAh + ar * GPAD + ac);
    uint4* sAlp = (uint4*)(sAl + ar * GPAD + ac);
    uint4* sBhp = (uint4*)(sBh + br * GPAD + bc);
    uint4* sBlp = (uint4*)(sBl + br * GPAD + bc);

    // warp tiling: 4x4 warps, each 32 (m) x 64 (n)
    const int warp = tid >> 5;
    const int lane = tid & 31;
    const int wm   = (warp >> 2) * 32;   // 0,32,64,96
    const int wn   = (warp & 3) * 64;    // 0,64,128,192
    const int grp  = lane >> 2;          // 0..7
    const int tg   = lane & 3;           // 0..3

    float acc[2][8][4];
    #pragma unroll
    for (int mi = 0; mi < 2; mi++)
        #pragma unroll
        for (int ni = 0; ni < 8; ni++)
            #pragma unroll
            for (int c = 0; c < 4; c++) acc[mi][ni][c] = 0.0f;

    uint4 ra  = pAh[0], rb  = pAl[0];
    uint4 rc0 = pBh[0], rc1 = pBh[1];
    uint4 rd0 = pBl[0], rd1 = pBl[1];

    const int NITER = DMODEL / 32;       // 32 (uint4 stride per iter = 4)
    for (int kt = 0; kt < NITER; kt++) {
        *sAhp = ra;  *sAlp = rb;
        sBhp[0] = rc0; sBhp[1] = rc1;
        sBlp[0] = rd0; sBlp[1] = rd1;
        __syncthreads();

        if (kt + 1 < NITER) {
            ra  = pAh[(kt + 1) * 4];
            rb  = pAl[(kt + 1) * 4];
            rc0 = pBh[(kt + 1) * 4];
            rc1 = pBh[(kt + 1) * 4 + 1];
            rd0 = pBl[(kt + 1) * 4];
            rd1 = pBl[(kt + 1) * 4 + 1];
        }

        #pragma unroll
        for (int kk = 0; kk < 32; kk += 16) {
            const int arow0 = (wm + grp) * GPAD + kk + tg * 2;
            const int arow1 = (wm + 8 + grp) * GPAD + kk + tg * 2;
            const int arow2 = (wm + 16 + grp) * GPAD + kk + tg * 2;
            const int arow3 = (wm + 24 + grp) * GPAD + kk + tg * 2;

            uint32_t ah[2][4], al[2][4];
            ah[0][0] = *(const uint32_t*)(sAh + arow0);
            ah[0][1] = *(const uint32_t*)(sAh + arow1);
            ah[0][2] = *(const uint32_t*)(sAh + arow0 + 8);
            ah[0][3] = *(const uint32_t*)(sAh + arow1 + 8);
            ah[1][0] = *(const uint32_t*)(sAh + arow2);
            ah[1][1] = *(const uint32_t*)(sAh + arow3);
            ah[1][2] = *(const uint32_t*)(sAh + arow2 + 8);
            ah[1][3] = *(const uint32_t*)(sAh + arow3 + 8);
            al[0][0] = *(const uint32_t*)(sAl + arow0);
            al[0][1] = *(const uint32_t*)(sAl + arow1);
            al[0][2] = *(const uint32_t*)(sAl + arow0 + 8);
            al[0][3] = *(const uint32_t*)(sAl + arow1 + 8);
            al[1][0] = *(const uint32_t*)(sAl + arow2);
            al[1][1] = *(const uint32_t*)(sAl + arow3);
            al[1][2] = *(const uint32_t*)(sAl + arow2 + 8);
            al[1][3] = *(const uint32_t*)(sAl + arow3 + 8);

            // B n-tiles in two groups of 4 to bound live registers
            #pragma unroll
            for (int ng = 0; ng < 2; ng++) {
                uint32_t bh[4][2], bl[4][2];
                #pragma unroll
                for (int nj = 0; nj < 4; nj++) {
                    const int bcol = (wn + (ng * 4 + nj) * 8 + grp) * GPAD + kk + tg * 2;
                    bh[nj][0] = *(const uint32_t*)(sBh + bcol);
                    bh[nj][1] = *(const uint32_t*)(sBh + bcol + 8);
                    bl[nj][0] = *(const uint32_t*)(sBl + bcol);
                    bl[nj][1] = *(const uint32_t*)(sBl + bcol + 8);
                }
                #pragma unroll
                for (int mi = 0; mi < 2; mi++)
                    #pragma unroll
                    for (int nj = 0; nj < 4; nj++) {
                        float* cc = acc[mi][ng * 4 + nj];
                        mma16816(cc[0], cc[1], cc[2], cc[3],
                                 ah[mi][0], ah[mi][1], ah[mi][2], ah[mi][3],
                                 bh[nj][0], bh[nj][1]);
                        mma16816(cc[0], cc[1], cc[2], cc[3],
                                 al[mi][0], al[mi][1], al[mi][2], al[mi][3],
                                 bh[nj][0], bh[nj][1]);
                        mma16816(cc[0], cc[1], cc[2], cc[3],
                                 ah[mi][0], ah[mi][1], ah[mi][2], ah[mi][3],
                                 bl[nj][0], bl[nj][1]);
                    }
            }
        }
        __syncthreads();
    }

    #pragma unroll
    for (int mi = 0; mi < 2; mi++)
        #pragma unroll
        for (int ni = 0; ni < 8; ni++) {
            int row = bm0 + wm + mi * 16 + grp;
            int col = bn0 + wn + ni * 8 + tg * 2;
            float b0 = 0.f, b1 = 0.f;
            if (HASBIAS) { b0 = bias[col]; b1 = bias[col + 1]; }
            float2 v0 = make_float2(acc[mi][ni][0] + b0, acc[mi][ni][1] + b1);
            float2 v1 = make_float2(acc[mi][ni][2] + b0, acc[mi][ni][3] + b1);
            *(float2*)(C + row * DMODEL + col)       = v0;
            *(float2*)(C + (row + 8) * DMODEL + col) = v1;
        }
}

extern "C" __global__ void __launch_bounds__(512)
qkv_mma_kernel()
{
    const __nv_bfloat16* Wh = g_whi + blockIdx.z * DMODEL * DMODEL;
    const __nv_bfloat16* Wl = g_wlo + blockIdx.z * DMODEL * DMODEL;
    float* C = (blockIdx.z == 0) ? g_q : (blockIdx.z == 1) ? g_k : g_v;
    gemm_split_body<false>(g_xhi, g_xlo, Wh, Wl, C, nullptr);
}

extern "C" __global__ void __launch_bounds__(512)
out_mma_kernel(const float* __restrict__ bo, float* __restrict__ out)
{
    gemm_split_body<true>(g_aohi, g_aolo,
                          g_whi + 3 * DMODEL * DMODEL,
                          g_wlo + 3 * DMODEL * DMODEL, out, bo);
}

// ============================================================
// RoPE: cos/sin table in double (phase accuracy), then apply.
// ============================================================
extern "C" __global__ void __launch_bounds__(256)
rope_table_kernel()
{
    int idx = blockIdx.x * 256 + threadIdx.x;   // < 2048*32
    int t = idx >> 5;
    int d = idx & 31;
    double freq = pow(10000.0, -(double)d / 32.0);
    double ang  = (double)t * freq;
    double sd, cd;
    sincos(ang, &sd, &cd);
    g_cos[idx] = (float)cd;
    g_sin[idx] = (float)sd;
}

extern "C" __global__ void __launch_bounds__(256)
rope_apply_kernel()
{
    int idx = blockIdx.x * 256 + threadIdx.x;   // < 4096*16*32
    int d  = idx & 31;
    int h  = (idx >> 5) & 15;
    int bt = idx >> 9;
    int t  = bt & (TDIM - 1);

    float c = g_cos[t * 32 + d];
    float s = g_sin[t * 32 + d];

    int base = bt * DMODEL + h * DH + d;

    float a = g_q[base], b = g_q[base + 32];
    g_q[base]      = a * c - b * s;
    g_q[base + 32] = b * c + a * s;

    a = g_k[base]; b = g_k[base + 32];
    g_k[base]      = a * c - b * s;
    g_k[base + 32] = b * c + a * s;
}

// ============================================================
// Sliding-window attention, register-tiled, 512 threads.
// 64-query tile, 192-key window.
// Phase 1: scores, 4q x 6k per thread.
// Phase 2: softmax, 8 threads per row + shfl reduce.
// Phase 3: PV, 4q x 2d per thread; emits split-bf16 output.
// smem: Q[64][65] K[192][65] V[192][65] S[64][193]  (165888 B)
// ============================================================
#define ATTN_THREADS 512
#define ATTN_SMEM_FLOATS (64*65 + 192*65 + 192*65 + 64*193)
#define ATTN_SMEM_BYTES  (ATTN_SMEM_FLOATS * 4)

extern "C" __global__ void __launch_bounds__(ATTN_THREADS)
attn_kernel()
{
    extern __shared__ float sm[];
    float* Qs = sm;                    // [64][65]
    float* Ks = Qs + 64 * 65;          // [192][65]
    float* Vs = Ks + 192 * 65;         // [192][65]
    float* Ss = Vs + 192 * 65;         // [64][193]

    const int tid = threadIdx.x;
    const int q0  = blockIdx.x * 64;
    const int h   = blockIdx.y;
    const int b   = blockIdx.z;

    const int k0 = max(0, q0 - (WIN - 1));
    const int nk = q0 + 64 - k0;       // <= 192

    const float* Qg = g_q + (b * TDIM + q0) * DMODEL + h * DH;
    const float* Kg = g_k + (b * TDIM + k0) * DMODEL + h * DH;
    const float* Vg = g_v + (b * TDIM + k0) * DMODEL + h * DH;

    for (int idx = tid; idx < 64 * 16; idx += ATTN_THREADS) {
        int i = idx >> 4, c = (idx & 15) * 4;
        float4 v = *(const float4*)(Qg + i * DMODEL + c);
        float* p = Qs + i * 65 + c;
        p[0] = v.x; p[1] = v.y; p[2] = v.z; p[3] = v.w;
    }
    for (int idx = tid; idx < nk * 16; idx += ATTN_THREADS) {
        int j = idx >> 4, c = (idx & 15) * 4;
        float4 vk = *(const float4*)(Kg + j * DMODEL + c);
        float4 vv = *(const float4*)(Vg + j * DMODEL + c);
        float* pk = Ks + j * 65 + c;
        float* pv = Vs + j * 65 + c;
        pk[0] = vk.x; pk[1] = vk.y; pk[2] = vk.z; pk[3] = vk.w;
        pv[0] = vv.x; pv[1] = vv.y; pv[2] = vv.z; pv[3] = vv.w;
    }
    for (int idx = nk * 64 + tid; idx < 192 * 64; idx += ATTN_THREADS) {
        int j = idx >> 6, d = idx & 63;
        Vs[j * 65 + d] = 0.0f;
    }
    __syncthreads();

    // ---- Phase 1: scores, 4 queries x 6 keys per thread ----
    {
        const int ty = tid >> 5;       // 0..15 -> queries ty*4 .. +3
        const int tx = tid & 31;       // keys tx + 32*u, u=0..5
        float acc[4][6];
        #pragma unroll
        for (int i = 0; i < 4; i++)
            #pragma unroll
            for (int u = 0; u < 6; u++) acc[i][u] = 0.0f;

        const float* qb = Qs + (ty * 4) * 65;
        const float* kb = Ks + tx * 65;

        #pragma unroll 4
        for (int d = 0; d < DH; d++) {
            float qv[4];
            #pragma unroll
            for (int i = 0; i < 4; i++) qv[i] = qb[i * 65 + d];
            float kv[6];
            #pragma unroll
            for (int u = 0; u < 6; u++) kv[u] = kb[u * 32 * 65 + d];
            #pragma unroll
            for (int i = 0; i < 4; i++)
                #pragma unroll
                for (int u = 0; u < 6; u++)
                    acc[i][u] = fmaf(qv[i], kv[u], acc[i][u]);
        }

        #pragma unroll
        for (int i = 0; i < 4; i++) {
            int iq = q0 + ty * 4 + i;
            #pragma unroll
            for (int u = 0; u < 6; u++) {
                int j  = tx + 32 * u;
                int jg = k0 + j;
                bool valid = (j < nk) && (jg <= iq) && (jg >= iq - (WIN - 1));
                Ss[(ty * 4 + i) * 193 + j] = valid ? acc[i][u] * 0.125f : -INFINITY;
            }
        }
    }
    __syncthreads();

    // ---- Phase 2: softmax, 8 threads per row ----
    {
        const int row = tid >> 3;
        const int g   = tid & 7;
        float* sp = Ss + row * 193;
        float m = -INFINITY;
        for (int j = g; j < 192; j += 8) m = fmaxf(m, sp[j]);
        m = fmaxf(m, __shfl_xor_sync(0xffffffffu, m, 1));
        m = fmaxf(m, __shfl_xor_sync(0xffffffffu, m, 2));
        m = fmaxf(m, __shfl_xor_sync(0xffffffffu, m, 4));
        float sum = 0.0f;
        for (int j = g; j < 192; j += 8) {
            float e = __expf(sp[j] - m);
            sp[j] = e;
            sum += e;
        }
        sum += __shfl_xor_sync(0xffffffffu, sum, 1);
        sum += __shfl_xor_sync(0xffffffffu, sum, 2);
        sum += __shfl_xor_sync(0xffffffffu, sum, 4);
        float inv = 1.0f / sum;
        for (int j = g; j < 192; j += 8) sp[j] *= inv;
    }
    __syncthreads();

    // ---- Phase 3: O = P @ V, 4 rows x 2 cols per thread ----
    {
        const int ty = tid >> 5;       // rows ty*4 .. +3
        const int tx = tid & 31;       // cols tx + 32*dd, dd=0..1
        float acc[4][2];
        #pragma unroll
        for (int i = 0; i < 4; i++) {
            acc[i][0] = 0.0f; acc[i][1] = 0.0f;
        }

        const float* pb = Ss + (ty * 4) * 193;
        const float* vb = Vs + tx;

        #pragma unroll 4
        for (int k = 0; k < 192; k++) {
            float v0 = vb[k * 65];
            float v1 = vb[k * 65 + 32];
            #pragma unroll
            for (int i = 0; i < 4; i++) {
                float p = pb[i * 193 + k];
                acc[i][0] = fmaf(p, v0, acc[i][0]);
                acc[i][1] = fmaf(p, v1, acc[i][1]);
            }
        }

        long base = (long)(b * TDIM + q0) * DMODEL + h * DH;
        #pragma unroll
        for (int i = 0; i < 4; i++)
            #pragma unroll
            for (int d = 0; d < 2; d++) {
                float v = acc[i][d];
                __nv_bfloat16 hh = __float2bfloat16(v);
                float r = v - __bfloat162float(hh);
                long off = base + (long)(ty * 4 + i) * DMODEL + tx + 32 * d;
                g_aohi[off] = hh;
                g_aolo[off] = __float2bfloat16(r);
            }
    }
}

// ============================================================
// launch
// ============================================================
extern "C" void kernel_launch(void* const* d_in, const int* in_sizes, int n_in,
                              void* d_out, int out_size)
{
    const float* X  = (const float*)d_in[0];
    const float* Wq = (const float*)d_in[1];
    const float* Wk = (const float*)d_in[2];
    const float* Wv = (const float*)d_in[3];
    const float* Wo = (const float*)d_in[4];
    const float* bo = (const float*)d_in[5];
    float* out = (float*)d_out;

    cudaFuncSetAttribute(attn_kernel,
                         cudaFuncAttributeMaxDynamicSharedMemorySize,
                         ATTN_SMEM_BYTES);
    cudaFuncSetAttribute(qkv_mma_kernel,
                         cudaFuncAttributeMaxDynamicSharedMemorySize,
                         GEMM_SMEM_BYTES);
    cudaFuncSetAttribute(out_mma_kernel,
                         cudaFuncAttributeMaxDynamicSharedMemorySize,
                         GEMM_SMEM_BYTES);

    __nv_bfloat16 *xhi, *xlo, *whi, *wlo;
    cudaGetSymbolAddress((void**)&xhi, g_xhi);
    cudaGetSymbolAddress((void**)&xlo, g_xlo);
    cudaGetSymbolAddress((void**)&whi, g_whi);
    cudaGetSymbolAddress((void**)&wlo, g_wlo);

    rope_table_kernel<<<(TDIM * 32) / 256, 256>>>();
    // 5 tensors, vectorized: grid.x sized for X (4M elems / (256*4))
    cvt4_kernel<<<dim3((MTOT * DMODEL) / 1024, 5, 1), 256>>>(
        X, Wq, Wk, Wv, Wo, xhi, xlo, whi, wlo);

    qkv_mma_kernel<<<dim3(DMODEL / 256, MTOT / 128, 3), 512, GEMM_SMEM_BYTES>>>();
    rope_apply_kernel<<<(MTOT * NH * 32) / 256, 256>>>();
    attn_kernel<<<dim3(TDIM / 64, NH, BDIM), ATTN_THREADS, ATTN_SMEM_BYTES>>>();
    out_mma_kernel<<<dim3(DMODEL / 256, MTOT / 128, 1), 512, GEMM_SMEM_BYTES>>>(bo, out);
}

// round 12
// speedup vs baseline: 2.9214x; 1.0030x over previous
#include <cuda_runtime.h>
#include <cuda_bf16.h>
#include <math.h>
#include <stdint.h>

#define TDIM   2048
#define BDIM   2
#define DMODEL 1024
#define NH     16
#define DH     64
#define WIN    128
#define MTOT   (BDIM*TDIM)          // 4096 rows

// -------- scratch (device globals: allocation-free) --------
__device__ float g_q [MTOT*DMODEL];
__device__ float g_k [MTOT*DMODEL];
__device__ float g_v [MTOT*DMODEL];
__device__ float g_cos[TDIM*32];
__device__ float g_sin[TDIM*32];

// bf16 split operands
__device__ __nv_bfloat16 g_xhi [MTOT*DMODEL];
__device__ __nv_bfloat16 g_xlo [MTOT*DMODEL];
__device__ __nv_bfloat16 g_whi [4*DMODEL*DMODEL];   // q,k,v,o
__device__ __nv_bfloat16 g_wlo [4*DMODEL*DMODEL];
__device__ __nv_bfloat16 g_aohi[MTOT*DMODEL];
__device__ __nv_bfloat16 g_aolo[MTOT*DMODEL];

// ============================================================
// fp32 -> (hi, lo) bf16 split, vectorized, all 5 tensors in one
// launch (grid.y selects tensor).
// ============================================================
extern "C" __global__ void __launch_bounds__(256)
cvt4_kernel(const float* __restrict__ X,
            const float* __restrict__ W0, const float* __restrict__ W1,
            const float* __restrict__ W2, const float* __restrict__ W3,
            __nv_bfloat16* __restrict__ xhi, __nv_bfloat16* __restrict__ xlo,
            __nv_bfloat16* __restrict__ whi, __nv_bfloat16* __restrict__ wlo)
{
    const int NW = DMODEL * DMODEL;
    const float* src;
    __nv_bfloat16 *hi, *lo;
    int n;
    int y = blockIdx.y;
    if (y == 0) { src = X;  hi = xhi; lo = xlo; n = MTOT * DMODEL; }
    else {
        src = (y == 1) ? W0 : (y == 2) ? W1 : (y == 3) ? W2 : W3;
        hi = whi + (y - 1) * NW;
        lo = wlo + (y - 1) * NW;
        n = NW;
    }
    int i = (blockIdx.x * 256 + threadIdx.x) * 4;
    if (i >= n) return;
    float4 v = *(const float4*)(src + i);
    __nv_bfloat16 h0 = __float2bfloat16(v.x);
    __nv_bfloat16 h1 = __float2bfloat16(v.y);
    __nv_bfloat16 h2 = __float2bfloat16(v.z);
    __nv_bfloat16 h3 = __float2bfloat16(v.w);
    __nv_bfloat16 l0 = __float2bfloat16(v.x - __bfloat162float(h0));
    __nv_bfloat16 l1 = __float2bfloat16(v.y - __bfloat162float(h1));
    __nv_bfloat16 l2 = __float2bfloat16(v.z - __bfloat162float(h2));
    __nv_bfloat16 l3 = __float2bfloat16(v.w - __bfloat162float(h3));
    ushort4 ph = make_ushort4(*(unsigned short*)&h0, *(unsigned short*)&h1,
                              *(unsigned short*)&h2, *(unsigned short*)&h3);
    ushort4 pl = make_ushort4(*(unsigned short*)&l0, *(unsigned short*)&l1,
                              *(unsigned short*)&l2, *(unsigned short*)&l3);
    *(ushort4*)(hi + i) = ph;
    *(ushort4*)(lo + i) = pl;
}

// ============================================================
// Split-bf16 GEMM on tensor cores (mma.sync m16n8k16):
//   C[m][n] = sum_k A[m][k]*W[n][k]  via Ahi*Bhi + Ahi*Blo + Alo*Bhi
// CTA 128x256, K-chunk 32, 512 threads (16 warps 4x4), warp 32x64.
// ============================================================
#define GPAD 40
#define GEMM_SMEM_BYTES ((2*128*GPAD + 2*256*GPAD) * 2)

__device__ __forceinline__ void mma16816(
    float& c0, float& c1, float& c2, float& c3,
    uint32_t a0, uint32_t a1, uint32_t a2, uint32_t a3,
    uint32_t b0, uint32_t b1)
{
    asm volatile(
        "mma.sync.aligned.m16n8k16.row.col.f32.bf16.bf16.f32 "
        "{%0,%1,%2,%3}, {%4,%5,%6,%7}, {%8,%9}, {%0,%1,%2,%3};"
        : "+f"(c0), "+f"(c1), "+f"(c2), "+f"(c3)
        : "r"(a0), "r"(a1), "r"(a2), "r"(a3), "r"(b0), "r"(b1));
}

template<bool HASBIAS>
__device__ __forceinline__ void gemm_split_body(
    const __nv_bfloat16* __restrict__ Ahi, const __nv_bfloat16* __restrict__ Alo,
    const __nv_bfloat16* __restrict__ Bhi, const __nv_bfloat16* __restrict__ Blo,
    float* __restrict__ C, const float* __restrict__ bias)
{
    extern __shared__ __align__(16) __nv_bfloat16 gsm[];
    __nv_bfloat16* sAh = gsm;
    __nv_bfloat16* sAl = sAh + 128 * GPAD;
    __nv_bfloat16* sBh = sAl + 128 * GPAD;
    __nv_bfloat16* sBl = sBh + 256 * GPAD;

    const int tid = threadIdx.x;
    const int bm0 = blockIdx.y * 128;
    const int bn0 = blockIdx.x * 256;

    const int ar = tid >> 2;
    const int ac = (tid & 3) * 8;
    const int br = tid >> 1;
    const int bc = (tid & 1) * 16;

    const uint4* pAh = (const uint4*)(Ahi + (bm0 + ar) * DMODEL + ac);
    const uint4* pAl = (const uint4*)(Alo + (bm0 + ar) * DMODEL + ac);
    const uint4* pBh = (const uint4*)(Bhi + (bn0 + br) * DMODEL + bc);
    const uint4* pBl = (const uint4*)(Blo + (bn0 + br) * DMODEL + bc);

    uint4* sAhp = (uint4*)(sAh + ar * GPAD + ac);
    uint4* sAlp = (uint4*)(sAl + ar * GPAD + ac);
    uint4* sBhp = (uint4*)(sBh + br * GPAD + bc);
    uint4* sBlp = (uint4*)(sBl + br * GPAD + bc);

    const int warp = tid >> 5;
    const int lane = tid & 31;
    const int wm   = (warp >> 2) * 32;
    const int wn   = (warp & 3) * 64;
    const int grp  = lane >> 2;
    const int tg   = lane & 3;

    float acc[2][8][4];
    #pragma unroll
    for (int mi = 0; mi < 2; mi++)
        #pragma unroll
        for (int ni = 0; ni < 8; ni++)
            #pragma unroll
            for (int c = 0; c < 4; c++) acc[mi][ni][c] = 0.0f;

    uint4 ra  = pAh[0], rb  = pAl[0];
    uint4 rc0 = pBh[0], rc1 = pBh[1];
    uint4 rd0 = pBl[0], rd1 = pBl[1];

    const int NITER = DMODEL / 32;
    for (int kt = 0; kt < NITER; kt++) {
        *sAhp = ra;  *sAlp = rb;
        sBhp[0] = rc0; sBhp[1] = rc1;
        sBlp[0] = rd0; sBlp[1] = rd1;
        __syncthreads();

        if (kt + 1 < NITER) {
            ra  = pAh[(kt + 1) * 4];
            rb  = pAl[(kt + 1) * 4];
            rc0 = pBh[(kt + 1) * 4];
            rc1 = pBh[(kt + 1) * 4 + 1];
            rd0 = pBl[(kt + 1) * 4];
            rd1 = pBl[(kt + 1) * 4 + 1];
        }

        #pragma unroll
        for (int kk = 0; kk < 32; kk += 16) {
            const int arow0 = (wm + grp) * GPAD + kk + tg * 2;
            const int arow1 = (wm + 8 + grp) * GPAD + kk + tg * 2;
            const int arow2 = (wm + 16 + grp) * GPAD + kk + tg * 2;
            const int arow3 = (wm + 24 + grp) * GPAD + kk + tg * 2;

            uint32_t ah[2][4], al[2][4];
            ah[0][0] = *(const uint32_t*)(sAh + arow0);
            ah[0][1] = *(const uint32_t*)(sAh + arow1);
            ah[0][2] = *(const uint32_t*)(sAh + arow0 + 8);
            ah[0][3] = *(const uint32_t*)(sAh + arow1 + 8);
            ah[1][0] = *(const uint32_t*)(sAh + arow2);
            ah[1][1] = *(const uint32_t*)(sAh + arow3);
            ah[1][2] = *(const uint32_t*)(sAh + arow2 + 8);
            ah[1][3] = *(const uint32_t*)(sAh + arow3 + 8);
            al[0][0] = *(const uint32_t*)(sAl + arow0);
            al[0][1] = *(const uint32_t*)(sAl + arow1);
            al[0][2] = *(const uint32_t*)(sAl + arow0 + 8);
            al[0][3] = *(const uint32_t*)(sAl + arow1 + 8);
            al[1][0] = *(const uint32_t*)(sAl + arow2);
            al[1][1] = *(const uint32_t*)(sAl + arow3);
            al[1][2] = *(const uint32_t*)(sAl + arow2 + 8);
            al[1][3] = *(const uint32_t*)(sAl + arow3 + 8);

            #pragma unroll
            for (int ng = 0; ng < 2; ng++) {
                uint32_t bh[4][2], bl[4][2];
                #pragma unroll
                for (int nj = 0; nj < 4; nj++) {
                    const int bcol = (wn + (ng * 4 + nj) * 8 + grp) * GPAD + kk + tg * 2;
                    bh[nj][0] = *(const uint32_t*)(sBh + bcol);
                    bh[nj][1] = *(const uint32_t*)(sBh + bcol + 8);
                    bl[nj][0] = *(const uint32_t*)(sBl + bcol);
                    bl[nj][1] = *(const uint32_t*)(sBl + bcol + 8);
                }
                #pragma unroll
                for (int mi = 0; mi < 2; mi++)
                    #pragma unroll
                    for (int nj = 0; nj < 4; nj++) {
                        float* cc = acc[mi][ng * 4 + nj];
                        mma16816(cc[0], cc[1], cc[2], cc[3],
                                 ah[mi][0], ah[mi][1], ah[mi][2], ah[mi][3],
                                 bh[nj][0], bh[nj][1]);
                        mma16816(cc[0], cc[1], cc[2], cc[3],
                                 al[mi][0], al[mi][1], al[mi][2], al[mi][3],
                                 bh[nj][0], bh[nj][1]);
                        mma16816(cc[0], cc[1], cc[2], cc[3],
                                 ah[mi][0], ah[mi][1], ah[mi][2], ah[mi][3],
                                 bl[nj][0], bl[nj][1]);
                    }
            }
        }
        __syncthreads();
    }

    #pragma unroll
    for (int mi = 0; mi < 2; mi++)
        #pragma unroll
        for (int ni = 0; ni < 8; ni++) {
            int row = bm0 + wm + mi * 16 + grp;
            int col = bn0 + wn + ni * 8 + tg * 2;
            float b0 = 0.f, b1 = 0.f;
            if (HASBIAS) { b0 = bias[col]; b1 = bias[col + 1]; }
            float2 v0 = make_float2(acc[mi][ni][0] + b0, acc[mi][ni][1] + b1);
            float2 v1 = make_float2(acc[mi][ni][2] + b0, acc[mi][ni][3] + b1);
            *(float2*)(C + row * DMODEL + col)       = v0;
            *(float2*)(C + (row + 8) * DMODEL + col) = v1;
        }
}

extern "C" __global__ void __launch_bounds__(512)
qkv_mma_kernel()
{
    const __nv_bfloat16* Wh = g_whi + blockIdx.z * DMODEL * DMODEL;
    const __nv_bfloat16* Wl = g_wlo + blockIdx.z * DMODEL * DMODEL;
    float* C = (blockIdx.z == 0) ? g_q : (blockIdx.z == 1) ? g_k : g_v;
    gemm_split_body<false>(g_xhi, g_xlo, Wh, Wl, C, nullptr);
}

extern "C" __global__ void __launch_bounds__(512)
out_mma_kernel(const float* __restrict__ bo, float* __restrict__ out)
{
    gemm_split_body<true>(g_aohi, g_aolo,
                          g_whi + 3 * DMODEL * DMODEL,
                          g_wlo + 3 * DMODEL * DMODEL, out, bo);
}

// ============================================================
// RoPE: cos/sin table in double (phase accuracy), then apply.
// ============================================================
extern "C" __global__ void __launch_bounds__(256)
rope_table_kernel()
{
    int idx = blockIdx.x * 256 + threadIdx.x;
    int t = idx >> 5;
    int d = idx & 31;
    double freq = pow(10000.0, -(double)d / 32.0);
    double ang  = (double)t * freq;
    double sd, cd;
    sincos(ang, &sd, &cd);
    g_cos[idx] = (float)cd;
    g_sin[idx] = (float)sd;
}

extern "C" __global__ void __launch_bounds__(256)
rope_apply_kernel()
{
    int idx = blockIdx.x * 256 + threadIdx.x;
    int d  = idx & 31;
    int h  = (idx >> 5) & 15;
    int bt = idx >> 9;
    int t  = bt & (TDIM - 1);

    float c = g_cos[t * 32 + d];
    float s = g_sin[t * 32 + d];

    int base = bt * DMODEL + h * DH + d;

    float a = g_q[base], b = g_q[base + 32];
    g_q[base]      = a * c - b * s;
    g_q[base + 32] = b * c + a * s;

    a = g_k[base]; b = g_k[base + 32];
    g_k[base]      = a * c - b * s;
    g_k[base + 32] = b * c + a * s;
}

// ============================================================
// Sliding-window attention on TENSOR CORES (split-bf16 MMA).
// 64-query tile, 192-key window, 512 threads (16 warps).
// Scores: M64 N192 K64, warp tile 16x48.
// PV:     M64 N64  K192, warp tile 16x16, V stored transposed.
// smem (bf16 halves unless noted):
//   Qh/Ql [64][72], Kh/Kl [192][72], Vth/Vtl [64][200],
//   Ph/Pl [64][200], S fp32 [64][193]   total 225536 B
// ============================================================
#define ATTN_THREADS 512
#define ATTN_SMEM_BYTES ((2*64*72 + 2*192*72 + 2*64*200 + 2*64*200)*2 + 64*193*4)

extern "C" __global__ void __launch_bounds__(ATTN_THREADS)
attn_kernel()
{
    extern __shared__ __align__(16) char smraw[];
    __nv_bfloat16* Qh  = (__nv_bfloat16*)smraw;
    __nv_bfloat16* Ql  = Qh  + 64 * 72;
    __nv_bfloat16* Kh  = Ql  + 64 * 72;
    __nv_bfloat16* Kl  = Kh  + 192 * 72;
    __nv_bfloat16* Vth = Kl  + 192 * 72;
    __nv_bfloat16* Vtl = Vth + 64 * 200;
    __nv_bfloat16* Ph  = Vtl + 64 * 200;
    __nv_bfloat16* Pl  = Ph  + 64 * 200;
    float*         S   = (float*)(Pl + 64 * 200);

    const int tid = threadIdx.x;
    const int q0  = blockIdx.x * 64;
    const int h   = blockIdx.y;
    const int b   = blockIdx.z;

    const int k0 = max(0, q0 - (WIN - 1));
    const int nk = q0 + 64 - k0;       // <= 192

    const float* Qg = g_q + (b * TDIM + q0) * DMODEL + h * DH;
    const float* Kg = g_k + (b * TDIM + k0) * DMODEL + h * DH;
    const float* Vg = g_v + (b * TDIM + k0) * DMODEL + h * DH;

    // ---- load + split Q, K; V transposed ----
    for (int idx = tid; idx < 64 * 64; idx += ATTN_THREADS) {
        int i = idx >> 6, d = idx & 63;
        float x = Qg[i * DMODEL + d];
        __nv_bfloat16 hh = __float2bfloat16(x);
        Qh[i * 72 + d] = hh;
        Ql[i * 72 + d] = __float2bfloat16(x - __bfloat162float(hh));
    }
    for (int idx = tid; idx < nk * 64; idx += ATTN_THREADS) {
        int j = idx >> 6, d = idx & 63;
        float x = Kg[j * DMODEL + d];
        __nv_bfloat16 hh = __float2bfloat16(x);
        Kh[j * 72 + d] = hh;
        Kl[j * 72 + d] = __float2bfloat16(x - __bfloat162float(hh));
        float y = Vg[j * DMODEL + d];
        __nv_bfloat16 vh = __float2bfloat16(y);
        Vth[d * 200 + j] = vh;
        Vtl[d * 200 + j] = __float2bfloat16(y - __bfloat162float(vh));
    }
    // zero tails (keys >= nk)
    const __nv_bfloat16 bz = __float2bfloat16(0.0f);
    for (int idx = tid; idx < (192 - nk) * 64; idx += ATTN_THREADS) {
        int j = nk + (idx >> 6), d = idx & 63;
        Kh[j * 72 + d] = bz;
        Kl[j * 72 + d] = bz;
        Vth[d * 200 + j] = bz;
        Vtl[d * 200 + j] = bz;
    }
    __syncthreads();

    const int warp = tid >> 5;
    const int lane = tid & 31;
    const int grp  = lane >> 2;          // 0..7
    const int tg   = lane & 3;           // 0..3
    const int wm   = (warp >> 2) * 16;   // 0,16,32,48

    // ---- Phase 1: scores = Q K^T (split-bf16 MMA), mask+scale ----
    {
        const int wn = (warp & 3) * 48;  // 0,48,96,144
        float acc[6][4];
        #pragma unroll
        for (int nj = 0; nj < 6; nj++)
            #pragma unroll
            for (int c = 0; c < 4; c++) acc[nj][c] = 0.0f;

        #pragma unroll
        for (int kk = 0; kk < 64; kk += 16) {
            const int ar0 = (wm + grp) * 72 + kk + tg * 2;
            const int ar1 = ar0 + 8 * 72;
            uint32_t ah0 = *(const uint32_t*)(Qh + ar0);
            uint32_t ah1 = *(const uint32_t*)(Qh + ar1);
            uint32_t ah2 = *(const uint32_t*)(Qh + ar0 + 8);
            uint32_t ah3 = *(const uint32_t*)(Qh + ar1 + 8);
            uint32_t al0 = *(const uint32_t*)(Ql + ar0);
            uint32_t al1 = *(const uint32_t*)(Ql + ar1);
            uint32_t al2 = *(const uint32_t*)(Ql + ar0 + 8);
            uint32_t al3 = *(const uint32_t*)(Ql + ar1 + 8);
            #pragma unroll
            for (int nj = 0; nj < 6; nj++) {
                const int bc = (wn + nj * 8 + grp) * 72 + kk + tg * 2;
                uint32_t bh0 = *(const uint32_t*)(Kh + bc);
                uint32_t bh1 = *(const uint32_t*)(Kh + bc + 8);
                uint32_t bl0 = *(const uint32_t*)(Kl + bc);
                uint32_t bl1 = *(const uint32_t*)(Kl + bc + 8);
                float* cc = acc[nj];
                mma16816(cc[0], cc[1], cc[2], cc[3], ah0, ah1, ah2, ah3, bh0, bh1);
                mma16816(cc[0], cc[1], cc[2], cc[3], al0, al1, al2, al3, bh0, bh1);
                mma16816(cc[0], cc[1], cc[2], cc[3], ah0, ah1, ah2, ah3, bl0, bl1);
            }
        }

        const int r0 = wm + grp, r1 = r0 + 8;
        const int iq0 = q0 + r0, iq1 = q0 + r1;
        #pragma unroll
        for (int nj = 0; nj < 6; nj++) {
            const int col = wn + nj * 8 + tg * 2;
            const int jg0 = k0 + col, jg1 = jg0 + 1;
            S[r0 * 193 + col]     = ((col     < nk) && (jg0 <= iq0) && (jg0 >= iq0 - (WIN-1)))
                                    ? acc[nj][0] * 0.125f : -INFINITY;
            S[r0 * 193 + col + 1] = ((col + 1 < nk) && (jg1 <= iq0) && (jg1 >= iq0 - (WIN-1)))
                                    ? acc[nj][1] * 0.125f : -INFINITY;
            S[r1 * 193 + col]     = ((col     < nk) && (jg0 <= iq1) && (jg0 >= iq1 - (WIN-1)))
                                    ? acc[nj][2] * 0.125f : -INFINITY;
            S[r1 * 193 + col + 1] = ((col + 1 < nk) && (jg1 <= iq1) && (jg1 >= iq1 - (WIN-1)))
                                    ? acc[nj][3] * 0.125f : -INFINITY;
        }
    }
    __syncthreads();

    // ---- Phase 2: softmax, 8 threads per row ----
    {
        const int row = tid >> 3;
        const int g   = tid & 7;
        float* sp = S + row * 193;
        float m = -INFINITY;
        for (int j = g; j < 192; j += 8) m = fmaxf(m, sp[j]);
        m = fmaxf(m, __shfl_xor_sync(0xffffffffu, m, 1));
        m = fmaxf(m, __shfl_xor_sync(0xffffffffu, m, 2));
        m = fmaxf(m, __shfl_xor_sync(0xffffffffu, m, 4));
        float sum = 0.0f;
        for (int j = g; j < 192; j += 8) {
            float e = __expf(sp[j] - m);
            sp[j] = e;
            sum += e;
        }
        sum += __shfl_xor_sync(0xffffffffu, sum, 1);
        sum += __shfl_xor_sync(0xffffffffu, sum, 2);
        sum += __shfl_xor_sync(0xffffffffu, sum, 4);
        float inv = 1.0f / sum;
        for (int j = g; j < 192; j += 8) sp[j] *= inv;
    }
    __syncthreads();

    // ---- split P to bf16 hi/lo ----
    for (int idx = tid; idx < 64 * 192; idx += ATTN_THREADS) {
        int i = idx / 192, j = idx - i * 192;
        float p = S[i * 193 + j];
        __nv_bfloat16 hh = __float2bfloat16(p);
        Ph[i * 200 + j] = hh;
        Pl[i * 200 + j] = __float2bfloat16(p - __bfloat162float(hh));
    }
    __syncthreads();

    // ---- Phase 3: O = P V (split-bf16 MMA over 192 keys) ----
    {
        const int wn = (warp & 3) * 16;  // 0,16,32,48
        float acc[2][4];
        #pragma unroll
        for (int nj = 0; nj < 2; nj++)
            #pragma unroll
            for (int c = 0; c < 4; c++) acc[nj][c] = 0.0f;

        #pragma unroll
        for (int kk = 0; kk < 192; kk += 16) {
            const int ar0 = (wm + grp) * 200 + kk + tg * 2;
            const int ar1 = ar0 + 8 * 200;
            uint32_t ah0 = *(const uint32_t*)(Ph + ar0);
            uint32_t ah1 = *(const uint32_t*)(Ph + ar1);
            uint32_t ah2 = *(const uint32_t*)(Ph + ar0 + 8);
            uint32_t ah3 = *(const uint32_t*)(Ph + ar1 + 8);
            uint32_t al0 = *(const uint32_t*)(Pl + ar0);
            uint32_t al1 = *(const uint32_t*)(Pl + ar1);
            uint32_t al2 = *(const uint32_t*)(Pl + ar0 + 8);
            uint32_t al3 = *(const uint32_t*)(Pl + ar1 + 8);
            #pragma unroll
            for (int nj = 0; nj < 2; nj++) {
                const int bc = (wn + nj * 8 + grp) * 200 + kk + tg * 2;
                uint32_t bh0 = *(const uint32_t*)(Vth + bc);
                uint32_t bh1 = *(const uint32_t*)(Vth + bc + 8);
                uint32_t bl0 = *(const uint32_t*)(Vtl + bc);
                uint32_t bl1 = *(const uint32_t*)(Vtl + bc + 8);
                float* cc = acc[nj];
                mma16816(cc[0], cc[1], cc[2], cc[3], ah0, ah1, ah2, ah3, bh0, bh1);
                mma16816(cc[0], cc[1], cc[2], cc[3], al0, al1, al2, al3, bh0, bh1);
                mma16816(cc[0], cc[1], cc[2], cc[3], ah0, ah1, ah2, ah3, bl0, bl1);
            }
        }

        const long base = (long)(b * TDIM + q0) * DMODEL + h * DH;
        const int r0 = wm + grp, r1 = r0 + 8;
        #pragma unroll
        for (int nj = 0; nj < 2; nj++) {
            const int col = wn + nj * 8 + tg * 2;
            #pragma unroll
            for (int rr = 0; rr < 2; rr++) {
                const int row = rr ? r1 : r0;
                float v0 = acc[nj][rr * 2];
                float v1 = acc[nj][rr * 2 + 1];
                __nv_bfloat16 h0 = __float2bfloat16(v0);
                __nv_bfloat16 h1 = __float2bfloat16(v1);
                __nv_bfloat16 l0 = __float2bfloat16(v0 - __bfloat162float(h0));
                __nv_bfloat16 l1 = __float2bfloat16(v1 - __bfloat162float(h1));
                long off = base + (long)row * DMODEL + col;
                *(__nv_bfloat162*)(g_aohi + off) = __nv_bfloat162(h0, h1);
                *(__nv_bfloat162*)(g_aolo + off) = __nv_bfloat162(l0, l1);
            }
        }
    }
}

// ============================================================
// launch
// ============================================================
extern "C" void kernel_launch(void* const* d_in, const int* in_sizes, int n_in,
                              void* d_out, int out_size)
{
    const float* X  = (const float*)d_in[0];
    const float* Wq = (const float*)d_in[1];
    const float* Wk = (const float*)d_in[2];
    const float* Wv = (const float*)d_in[3];
    const float* Wo = (const float*)d_in[4];
    const float* bo = (const float*)d_in[5];
    float* out = (float*)d_out;

    cudaFuncSetAttribute(attn_kernel,
                         cudaFuncAttributeMaxDynamicSharedMemorySize,
                         ATTN_SMEM_BYTES);
    cudaFuncSetAttribute(qkv_mma_kernel,
                         cudaFuncAttributeMaxDynamicSharedMemorySize,
                         GEMM_SMEM_BYTES);
    cudaFuncSetAttribute(out_mma_kernel,
                         cudaFuncAttributeMaxDynamicSharedMemorySize,
                         GEMM_SMEM_BYTES);

    __nv_bfloat16 *xhi, *xlo, *whi, *wlo;
    cudaGetSymbolAddress((void**)&xhi, g_xhi);
    cudaGetSymbolAddress((void**)&xlo, g_xlo);
    cudaGetSymbolAddress((void**)&whi, g_whi);
    cudaGetSymbolAddress((void**)&wlo, g_wlo);

    rope_table_kernel<<<(TDIM * 32) / 256, 256>>>();
    cvt4_kernel<<<dim3((MTOT * DMODEL) / 1024, 5, 1), 256>>>(
        X, Wq, Wk, Wv, Wo, xhi, xlo, whi, wlo);

    qkv_mma_kernel<<<dim3(DMODEL / 256, MTOT / 128, 3), 512, GEMM_SMEM_BYTES>>>();
    rope_apply_kernel<<<(MTOT * NH * 32) / 256, 256>>>();
    attn_kernel<<<dim3(TDIM / 64, NH, BDIM), ATTN_THREADS, ATTN_SMEM_BYTES>>>();
    out_mma_kernel<<<dim3(DMODEL / 256, MTOT / 128, 1), 512, GEMM_SMEM_BYTES>>>(bo, out);
}

// round 13
// speedup vs baseline: 3.1675x; 1.0842x over previous
#include <cuda_runtime.h>
#include <cuda_bf16.h>
#include <math.h>
#include <stdint.h>

#define TDIM   2048
#define BDIM   2
#define DMODEL 1024
#define NH     16
#define DH     64
#define WIN    128
#define MTOT   (BDIM*TDIM)          // 4096 rows

// -------- scratch (device globals: allocation-free) --------
__device__ float g_v  [MTOT*DMODEL];
__device__ float g_cos[TDIM*32];
__device__ float g_sin[TDIM*32];

// split-bf16 operands
__device__ __nv_bfloat16 g_xhi [MTOT*DMODEL];
__device__ __nv_bfloat16 g_xlo [MTOT*DMODEL];
__device__ __nv_bfloat16 g_whi [4*DMODEL*DMODEL];   // q,k,v,o
__device__ __nv_bfloat16 g_wlo [4*DMODEL*DMODEL];
__device__ __nv_bfloat16 g_qhi [MTOT*DMODEL];       // post-RoPE Q
__device__ __nv_bfloat16 g_qlo [MTOT*DMODEL];
__device__ __nv_bfloat16 g_khi [MTOT*DMODEL];       // post-RoPE K
__device__ __nv_bfloat16 g_klo [MTOT*DMODEL];
__device__ __nv_bfloat16 g_aohi[MTOT*DMODEL];
__device__ __nv_bfloat16 g_aolo[MTOT*DMODEL];

// ============================================================
// fp32 -> (hi, lo) bf16 split, vectorized, 5 tensors, one launch
// ============================================================
extern "C" __global__ void __launch_bounds__(256)
cvt4_kernel(const float* __restrict__ X,
            const float* __restrict__ W0, const float* __restrict__ W1,
            const float* __restrict__ W2, const float* __restrict__ W3,
            __nv_bfloat16* __restrict__ xhi, __nv_bfloat16* __restrict__ xlo,
            __nv_bfloat16* __restrict__ whi, __nv_bfloat16* __restrict__ wlo)
{
    const int NW = DMODEL * DMODEL;
    const float* src;
    __nv_bfloat16 *hi, *lo;
    int n;
    int y = blockIdx.y;
    if (y == 0) { src = X;  hi = xhi; lo = xlo; n = MTOT * DMODEL; }
    else {
        src = (y == 1) ? W0 : (y == 2) ? W1 : (y == 3) ? W2 : W3;
        hi = whi + (y - 1) * NW;
        lo = wlo + (y - 1) * NW;
        n = NW;
    }
    int i = (blockIdx.x * 256 + threadIdx.x) * 4;
    if (i >= n) return;
    float4 v = *(const float4*)(src + i);
    __nv_bfloat16 h0 = __float2bfloat16(v.x);
    __nv_bfloat16 h1 = __float2bfloat16(v.y);
    __nv_bfloat16 h2 = __float2bfloat16(v.z);
    __nv_bfloat16 h3 = __float2bfloat16(v.w);
    __nv_bfloat16 l0 = __float2bfloat16(v.x - __bfloat162float(h0));
    __nv_bfloat16 l1 = __float2bfloat16(v.y - __bfloat162float(h1));
    __nv_bfloat16 l2 = __float2bfloat16(v.z - __bfloat162float(h2));
    __nv_bfloat16 l3 = __float2bfloat16(v.w - __bfloat162float(h3));
    ushort4 ph = make_ushort4(*(unsigned short*)&h0, *(unsigned short*)&h1,
                              *(unsigned short*)&h2, *(unsigned short*)&h3);
    ushort4 pl = make_ushort4(*(unsigned short*)&l0, *(unsigned short*)&l1,
                              *(unsigned short*)&l2, *(unsigned short*)&l3);
    *(ushort4*)(hi + i) = ph;
    *(ushort4*)(lo + i) = pl;
}

// ============================================================
// RoPE cos/sin table (double precision phases)
// ============================================================
extern "C" __global__ void __launch_bounds__(256)
rope_table_kernel()
{
    int idx = blockIdx.x * 256 + threadIdx.x;
    int t = idx >> 5;
    int d = idx & 31;
    double freq = pow(10000.0, -(double)d / 32.0);
    double ang  = (double)t * freq;
    double sd, cd;
    sincos(ang, &sd, &cd);
    g_cos[idx] = (float)cd;
    g_sin[idx] = (float)sd;
}

// ============================================================
// Split-bf16 GEMM, cp.async double-buffered.
// CTA 128x256, K-chunk 32, 512 threads, warp 32x64.
// MODE 0: fp32 store; MODE 1: fp32+bias; MODE 2: RoPE + split store
// ============================================================
#define GPAD 40
#define BUFH (2*128*GPAD + 2*256*GPAD)     // halves per buffer = 30720
#define GEMM_SMEM_BYTES (2 * BUFH * 2)     // 122880

__device__ __forceinline__ void mma16816(
    float& c0, float& c1, float& c2, float& c3,
    uint32_t a0, uint32_t a1, uint32_t a2, uint32_t a3,
    uint32_t b0, uint32_t b1)
{
    asm volatile(
        "mma.sync.aligned.m16n8k16.row.col.f32.bf16.bf16.f32 "
        "{%0,%1,%2,%3}, {%4,%5,%6,%7}, {%8,%9}, {%0,%1,%2,%3};"
        : "+f"(c0), "+f"(c1), "+f"(c2), "+f"(c3)
        : "r"(a0), "r"(a1), "r"(a2), "r"(a3), "r"(b0), "r"(b1));
}

__device__ __forceinline__ void cp16(uint32_t dst, const void* src)
{
    asm volatile("cp.async.cg.shared.global [%0], [%1], 16;" :: "r"(dst), "l"(src));
}

__device__ __forceinline__ void store_split2(
    __nv_bfloat16* hi, __nv_bfloat16* lo, long off, float x, float y)
{
    __nv_bfloat16 h0 = __float2bfloat16(x);
    __nv_bfloat16 h1 = __float2bfloat16(y);
    __nv_bfloat16 l0 = __float2bfloat16(x - __bfloat162float(h0));
    __nv_bfloat16 l1 = __float2bfloat16(y - __bfloat162float(h1));
    *(__nv_bfloat162*)(hi + off) = __nv_bfloat162(h0, h1);
    *(__nv_bfloat162*)(lo + off) = __nv_bfloat162(l0, l1);
}

template<int MODE>
__device__ __forceinline__ void gemm_body(
    const __nv_bfloat16* __restrict__ Ahi, const __nv_bfloat16* __restrict__ Alo,
    const __nv_bfloat16* __restrict__ Bhi, const __nv_bfloat16* __restrict__ Blo,
    float* __restrict__ C, const float* __restrict__ bias,
    __nv_bfloat16* __restrict__ Chi, __nv_bfloat16* __restrict__ Clo)
{
    extern __shared__ __align__(16) __nv_bfloat16 gsm[];

    const int tid = threadIdx.x;
    const int bm0 = blockIdx.y * 128;
    const int bn0 = blockIdx.x * 256;

    const int ar = tid >> 2;             // 0..127
    const int ac = (tid & 3) * 8;        // 0,8,16,24
    const int br = tid >> 1;             // 0..255
    const int bc = (tid & 1) * 16;       // 0,16

    const __nv_bfloat16* gAh = Ahi + (bm0 + ar) * DMODEL + ac;
    const __nv_bfloat16* gAl = Alo + (bm0 + ar) * DMODEL + ac;
    const __nv_bfloat16* gBh = Bhi + (bn0 + br) * DMODEL + bc;
    const __nv_bfloat16* gBl = Blo + (bn0 + br) * DMODEL + bc;

    const int OFF_AL = 128 * GPAD;
    const int OFF_BH = 2 * 128 * GPAD;
    const int OFF_BL = OFF_BH + 256 * GPAD;

    uint32_t sbase = (uint32_t)__cvta_generic_to_shared(gsm);
    uint32_t dAh = sbase + 2 * (ar * GPAD + ac);
    uint32_t dAl = sbase + 2 * (OFF_AL + ar * GPAD + ac);
    uint32_t dBh = sbase + 2 * (OFF_BH + br * GPAD + bc);
    uint32_t dBl = sbase + 2 * (OFF_BL + br * GPAD + bc);

    const int warp = tid >> 5;
    const int lane = tid & 31;
    const int wm   = (warp >> 2) * 32;
    const int wn   = (warp & 3) * 64;
    const int grp  = lane >> 2;
    const int tg   = lane & 3;

    float acc[2][8][4];
    #pragma unroll
    for (int mi = 0; mi < 2; mi++)
        #pragma unroll
        for (int ni = 0; ni < 8; ni++)
            #pragma unroll
            for (int c = 0; c < 4; c++) acc[mi][ni][c] = 0.0f;

    // prologue: fill buffer 0
    {
        cp16(dAh, gAh);
        cp16(dAl, gAl);
        cp16(dBh, gBh); cp16(dBh + 16, gBh + 8);
        cp16(dBl, gBl); cp16(dBl + 16, gBl + 8);
        asm volatile("cp.async.commit_group;");
        asm volatile("cp.async.wait_group 0;");
    }
    __syncthreads();

    const int NITER = DMODEL / 32;       // 32
    int buf = 0;
    for (int kt = 0; kt < NITER; kt++) {
        if (kt + 1 < NITER) {
            uint32_t o = (buf ^ 1) * (BUFH * 2);
            const int ko = (kt + 1) * 32;
            cp16(dAh + o, gAh + ko);
            cp16(dAl + o, gAl + ko);
            cp16(dBh + o, gBh + ko); cp16(dBh + o + 16, gBh + ko + 8);
            cp16(dBl + o, gBl + ko); cp16(dBl + o + 16, gBl + ko + 8);
            asm volatile("cp.async.commit_group;");
        }

        const __nv_bfloat16* cAh = gsm + buf * BUFH;
        const __nv_bfloat16* cAl = cAh + OFF_AL;
        const __nv_bfloat16* cBh = gsm + buf * BUFH + OFF_BH;
        const __nv_bfloat16* cBl = gsm + buf * BUFH + OFF_BL;

        #pragma unroll
        for (int kk = 0; kk < 32; kk += 16) {
            const int arow0 = (wm + grp) * GPAD + kk + tg * 2;
            const int arow1 = arow0 + 8 * GPAD;
            const int arow2 = arow0 + 16 * GPAD;
            const int arow3 = arow0 + 24 * GPAD;

            uint32_t ah[2][4], al[2][4];
            ah[0][0] = *(const uint32_t*)(cAh + arow0);
            ah[0][1] = *(const uint32_t*)(cAh + arow1);
            ah[0][2] = *(const uint32_t*)(cAh + arow0 + 8);
            ah[0][3] = *(const uint32_t*)(cAh + arow1 + 8);
            ah[1][0] = *(const uint32_t*)(cAh + arow2);
            ah[1][1] = *(const uint32_t*)(cAh + arow3);
            ah[1][2] = *(const uint32_t*)(cAh + arow2 + 8);
            ah[1][3] = *(const uint32_t*)(cAh + arow3 + 8);
            al[0][0] = *(const uint32_t*)(cAl + arow0);
            al[0][1] = *(const uint32_t*)(cAl + arow1);
            al[0][2] = *(const uint32_t*)(cAl + arow0 + 8);
            al[0][3] = *(const uint32_t*)(cAl + arow1 + 8);
            al[1][0] = *(const uint32_t*)(cAl + arow2);
            al[1][1] = *(const uint32_t*)(cAl + arow3);
            al[1][2] = *(const uint32_t*)(cAl + arow2 + 8);
            al[1][3] = *(const uint32_t*)(cAl + arow3 + 8);

            #pragma unroll
            for (int ng = 0; ng < 2; ng++) {
                uint32_t bh[4][2], bl[4][2];
                #pragma unroll
                for (int nj = 0; nj < 4; nj++) {
                    const int bcol = (wn + (ng * 4 + nj) * 8 + grp) * GPAD + kk + tg * 2;
                    bh[nj][0] = *(const uint32_t*)(cBh + bcol);
                    bh[nj][1] = *(const uint32_t*)(cBh + bcol + 8);
                    bl[nj][0] = *(const uint32_t*)(cBl + bcol);
                    bl[nj][1] = *(const uint32_t*)(cBl + bcol + 8);
                }
                #pragma unroll
                for (int mi = 0; mi < 2; mi++)
                    #pragma unroll
                    for (int nj = 0; nj < 4; nj++) {
                        float* cc = acc[mi][ng * 4 + nj];
                        mma16816(cc[0], cc[1], cc[2], cc[3],
                                 ah[mi][0], ah[mi][1], ah[mi][2], ah[mi][3],
                                 bh[nj][0], bh[nj][1]);
                        mma16816(cc[0], cc[1], cc[2], cc[3],
                                 al[mi][0], al[mi][1], al[mi][2], al[mi][3],
                                 bh[nj][0], bh[nj][1]);
                        mma16816(cc[0], cc[1], cc[2], cc[3],
                                 ah[mi][0], ah[mi][1], ah[mi][2], ah[mi][3],
                                 bl[nj][0], bl[nj][1]);
                    }
            }
        }

        if (kt + 1 < NITER)
            asm volatile("cp.async.wait_group 0;");
        __syncthreads();
        buf ^= 1;
    }

    // ---- epilogue ----
    if (MODE == 2) {
        // fused RoPE + split-bf16 store. cols (ni) and (ni+4) are 32 apart
        // within the same 64-wide head -> rotation pair lives in-thread.
        #pragma unroll
        for (int mi = 0; mi < 2; mi++) {
            const int r0 = bm0 + wm + mi * 16 + grp;
            const int r1 = r0 + 8;
            const int t0 = r0 & (TDIM - 1);
            const int t1 = r1 & (TDIM - 1);
            #pragma unroll
            for (int ni = 0; ni < 4; ni++) {
                const int col = bn0 + wn + ni * 8 + tg * 2;
                const int d   = ni * 8 + tg * 2;          // 0..30, < 32
                float c00 = g_cos[t0 * 32 + d],     s00 = g_sin[t0 * 32 + d];
                float c01 = g_cos[t0 * 32 + d + 1], s01 = g_sin[t0 * 32 + d + 1];
                float c10 = g_cos[t1 * 32 + d],     s10 = g_sin[t1 * 32 + d];
                float c11 = g_cos[t1 * 32 + d + 1], s11 = g_sin[t1 * 32 + d + 1];
                float* pa = acc[mi][ni];
                float* pb = acc[mi][ni + 4];
                float a0 = pa[0], b0 = pb[0];
                float a1 = pa[1], b1 = pb[1];
                float a2 = pa[2], b2 = pb[2];
                float a3 = pa[3], b3 = pb[3];
                float na0 = a0 * c00 - b0 * s00, nb0 = b0 * c00 + a0 * s00;
                float na1 = a1 * c01 - b1 * s01, nb1 = b1 * c01 + a1 * s01;
                float na2 = a2 * c10 - b2 * s10, nb2 = b2 * c10 + a2 * s10;
                float na3 = a3 * c11 - b3 * s11, nb3 = b3 * c11 + a3 * s11;
                store_split2(Chi, Clo, (long)r0 * DMODEL + col,      na0, na1);
                store_split2(Chi, Clo, (long)r0 * DMODEL + col + 32, nb0, nb1);
                store_split2(Chi, Clo, (long)r1 * DMODEL + col,      na2, na3);
                store_split2(Chi, Clo, (long)r1 * DMODEL + col + 32, nb2, nb3);
            }
        }
    } else {
        #pragma unroll
        for (int mi = 0; mi < 2; mi++)
            #pragma unroll
            for (int ni = 0; ni < 8; ni++) {
                int row = bm0 + wm + mi * 16 + grp;
                int col = bn0 + wn + ni * 8 + tg * 2;
                float b0 = 0.f, b1 = 0.f;
                if (MODE == 1) { b0 = bias[col]; b1 = bias[col + 1]; }
                float2 v0 = make_float2(acc[mi][ni][0] + b0, acc[mi][ni][1] + b1);
                float2 v1 = make_float2(acc[mi][ni][2] + b0, acc[mi][ni][3] + b1);
                *(float2*)(C + row * DMODEL + col)       = v0;
                *(float2*)(C + (row + 8) * DMODEL + col) = v1;
            }
    }
}

extern "C" __global__ void __launch_bounds__(512)
qkv_mma_kernel()
{
    const int z = blockIdx.z;
    const __nv_bfloat16* Wh = g_whi + z * DMODEL * DMODEL;
    const __nv_bfloat16* Wl = g_wlo + z * DMODEL * DMODEL;
    if (z == 2) {
        gemm_body<0>(g_xhi, g_xlo, Wh, Wl, g_v, nullptr, nullptr, nullptr);
    } else {
        __nv_bfloat16* Chi = (z == 0) ? g_qhi : g_khi;
        __nv_bfloat16* Clo = (z == 0) ? g_qlo : g_klo;
        gemm_body<2>(g_xhi, g_xlo, Wh, Wl, nullptr, nullptr, Chi, Clo);
    }
}

extern "C" __global__ void __launch_bounds__(512)
out_mma_kernel(const float* __restrict__ bo, float* __restrict__ out)
{
    gemm_body<1>(g_aohi, g_aolo,
                 g_whi + 3 * DMODEL * DMODEL,
                 g_wlo + 3 * DMODEL * DMODEL, out, bo, nullptr, nullptr);
}

// ============================================================
// Sliding-window attention on tensor cores (split-bf16 MMA).
// Q/K arrive pre-split (post-RoPE) -> direct uint4 copies.
// ============================================================
#define ATTN_THREADS 512
#define ATTN_SMEM_BYTES ((2*64*72 + 2*192*72 + 2*64*200 + 2*64*200)*2 + 64*193*4)

extern "C" __global__ void __launch_bounds__(ATTN_THREADS)
attn_kernel()
{
    extern __shared__ __align__(16) char smraw[];
    __nv_bfloat16* Qh  = (__nv_bfloat16*)smraw;
    __nv_bfloat16* Ql  = Qh  + 64 * 72;
    __nv_bfloat16* Kh  = Ql  + 64 * 72;
    __nv_bfloat16* Kl  = Kh  + 192 * 72;
    __nv_bfloat16* Vth = Kl  + 192 * 72;
    __nv_bfloat16* Vtl = Vth + 64 * 200;
    __nv_bfloat16* Ph  = Vtl + 64 * 200;
    __nv_bfloat16* Pl  = Ph  + 64 * 200;
    float*         S   = (float*)(Pl + 64 * 200);

    const int tid = threadIdx.x;
    const int q0  = blockIdx.x * 64;
    const int h   = blockIdx.y;
    const int b   = blockIdx.z;

    const int k0 = max(0, q0 - (WIN - 1));
    const int nk = q0 + 64 - k0;       // <= 192

    const __nv_bfloat16* Qhg = g_qhi + ((long)(b * TDIM + q0)) * DMODEL + h * DH;
    const __nv_bfloat16* Qlg = g_qlo + ((long)(b * TDIM + q0)) * DMODEL + h * DH;
    const __nv_bfloat16* Khg = g_khi + ((long)(b * TDIM + k0)) * DMODEL + h * DH;
    const __nv_bfloat16* Klg = g_klo + ((long)(b * TDIM + k0)) * DMODEL + h * DH;
    const float*         Vg  = g_v   + ((long)(b * TDIM + k0)) * DMODEL + h * DH;

    // Q copy: 64 rows x 8 uint4
    for (int idx = tid; idx < 64 * 8; idx += ATTN_THREADS) {
        int row = idx >> 3, seg = idx & 7;
        ((uint4*)(Qh + row * 72))[seg] = ((const uint4*)(Qhg + row * DMODEL))[seg];
        ((uint4*)(Ql + row * 72))[seg] = ((const uint4*)(Qlg + row * DMODEL))[seg];
    }
    // K copy (+ zero tail): 192 rows x 8 uint4
    const uint4 z4 = make_uint4(0, 0, 0, 0);
    for (int idx = tid; idx < 192 * 8; idx += ATTN_THREADS) {
        int row = idx >> 3, seg = idx & 7;
        uint4 vh = z4, vl = z4;
        if (row < nk) {
            vh = ((const uint4*)(Khg + row * DMODEL))[seg];
            vl = ((const uint4*)(Klg + row * DMODEL))[seg];
        }
        ((uint4*)(Kh + row * 72))[seg] = vh;
        ((uint4*)(Kl + row * 72))[seg] = vl;
    }
    // V: fp32 -> split + transpose
    for (int idx = tid; idx < nk * 64; idx += ATTN_THREADS) {
        int j = idx >> 6, d = idx & 63;
        float y = Vg[j * DMODEL + d];
        __nv_bfloat16 vh = __float2bfloat16(y);
        Vth[d * 200 + j] = vh;
        Vtl[d * 200 + j] = __float2bfloat16(y - __bfloat162float(vh));
    }
    const __nv_bfloat16 bz = __float2bfloat16(0.0f);
    for (int idx = tid; idx < (192 - nk) * 64; idx += ATTN_THREADS) {
        int j = nk + (idx >> 6), d = idx & 63;
        Vth[d * 200 + j] = bz;
        Vtl[d * 200 + j] = bz;
    }
    __syncthreads();

    const int warp = tid >> 5;
    const int lane = tid & 31;
    const int grp  = lane >> 2;
    const int tg   = lane & 3;
    const int wm   = (warp >> 2) * 16;

    // ---- Phase 1: scores = Q K^T ----
    {
        const int wn = (warp & 3) * 48;
        float acc[6][4];
        #pragma unroll
        for (int nj = 0; nj < 6; nj++)
            #pragma unroll
            for (int c = 0; c < 4; c++) acc[nj][c] = 0.0f;

        #pragma unroll
        for (int kk = 0; kk < 64; kk += 16) {
            const int ar0 = (wm + grp) * 72 + kk + tg * 2;
            const int ar1 = ar0 + 8 * 72;
            uint32_t ah0 = *(const uint32_t*)(Qh + ar0);
            uint32_t ah1 = *(const uint32_t*)(Qh + ar1);
            uint32_t ah2 = *(const uint32_t*)(Qh + ar0 + 8);
            uint32_t ah3 = *(const uint32_t*)(Qh + ar1 + 8);
            uint32_t al0 = *(const uint32_t*)(Ql + ar0);
            uint32_t al1 = *(const uint32_t*)(Ql + ar1);
            uint32_t al2 = *(const uint32_t*)(Ql + ar0 + 8);
            uint32_t al3 = *(const uint32_t*)(Ql + ar1 + 8);
            #pragma unroll
            for (int nj = 0; nj < 6; nj++) {
                const int bc = (wn + nj * 8 + grp) * 72 + kk + tg * 2;
                uint32_t bh0 = *(const uint32_t*)(Kh + bc);
                uint32_t bh1 = *(const uint32_t*)(Kh + bc + 8);
                uint32_t bl0 = *(const uint32_t*)(Kl + bc);
                uint32_t bl1 = *(const uint32_t*)(Kl + bc + 8);
                float* cc = acc[nj];
                mma16816(cc[0], cc[1], cc[2], cc[3], ah0, ah1, ah2, ah3, bh0, bh1);
                mma16816(cc[0], cc[1], cc[2], cc[3], al0, al1, al2, al3, bh0, bh1);
                mma16816(cc[0], cc[1], cc[2], cc[3], ah0, ah1, ah2, ah3, bl0, bl1);
            }
        }

        const int r0 = wm + grp, r1 = r0 + 8;
        const int iq0 = q0 + r0, iq1 = q0 + r1;
        #pragma unroll
        for (int nj = 0; nj < 6; nj++) {
            const int col = wn + nj * 8 + tg * 2;
            const int jg0 = k0 + col, jg1 = jg0 + 1;
            S[r0 * 193 + col]     = ((col     < nk) && (jg0 <= iq0) && (jg0 >= iq0 - (WIN-1)))
                                    ? acc[nj][0] * 0.125f : -INFINITY;
            S[r0 * 193 + col + 1] = ((col + 1 < nk) && (jg1 <= iq0) && (jg1 >= iq0 - (WIN-1)))
                                    ? acc[nj][1] * 0.125f : -INFINITY;
            S[r1 * 193 + col]     = ((col     < nk) && (jg0 <= iq1) && (jg0 >= iq1 - (WIN-1)))
                                    ? acc[nj][2] * 0.125f : -INFINITY;
            S[r1 * 193 + col + 1] = ((col + 1 < nk) && (jg1 <= iq1) && (jg1 >= iq1 - (WIN-1)))
                                    ? acc[nj][3] * 0.125f : -INFINITY;
        }
    }
    __syncthreads();

    // ---- Phase 2: softmax, 8 threads/row ----
    {
        const int row = tid >> 3;
        const int g   = tid & 7;
        float* sp = S + row * 193;
        float m = -INFINITY;
        for (int j = g; j < 192; j += 8) m = fmaxf(m, sp[j]);
        m = fmaxf(m, __shfl_xor_sync(0xffffffffu, m, 1));
        m = fmaxf(m, __shfl_xor_sync(0xffffffffu, m, 2));
        m = fmaxf(m, __shfl_xor_sync(0xffffffffu, m, 4));
        float sum = 0.0f;
        for (int j = g; j < 192; j += 8) {
            float e = __expf(sp[j] - m);
            sp[j] = e;
            sum += e;
        }
        sum += __shfl_xor_sync(0xffffffffu, sum, 1);
        sum += __shfl_xor_sync(0xffffffffu, sum, 2);
        sum += __shfl_xor_sync(0xffffffffu, sum, 4);
        float inv = 1.0f / sum;
        for (int j = g; j < 192; j += 8) sp[j] *= inv;
    }
    __syncthreads();

    // ---- split P ----
    for (int idx = tid; idx < 64 * 192; idx += ATTN_THREADS) {
        int i = idx / 192, j = idx - i * 192;
        float p = S[i * 193 + j];
        __nv_bfloat16 hh = __float2bfloat16(p);
        Ph[i * 200 + j] = hh;
        Pl[i * 200 + j] = __float2bfloat16(p - __bfloat162float(hh));
    }
    __syncthreads();

    // ---- Phase 3: O = P V ----
    {
        const int wn = (warp & 3) * 16;
        float acc[2][4];
        #pragma unroll
        for (int nj = 0; nj < 2; nj++)
            #pragma unroll
            for (int c = 0; c < 4; c++) acc[nj][c] = 0.0f;

        #pragma unroll
        for (int kk = 0; kk < 192; kk += 16) {
            const int ar0 = (wm + grp) * 200 + kk + tg * 2;
            const int ar1 = ar0 + 8 * 200;
            uint32_t ah0 = *(const uint32_t*)(Ph + ar0);
            uint32_t ah1 = *(const uint32_t*)(Ph + ar1);
            uint32_t ah2 = *(const uint32_t*)(Ph + ar0 + 8);
            uint32_t ah3 = *(const uint32_t*)(Ph + ar1 + 8);
            uint32_t al0 = *(const uint32_t*)(Pl + ar0);
            uint32_t al1 = *(const uint32_t*)(Pl + ar1);
            uint32_t al2 = *(const uint32_t*)(Pl + ar0 + 8);
            uint32_t al3 = *(const uint32_t*)(Pl + ar1 + 8);
            #pragma unroll
            for (int nj = 0; nj < 2; nj++) {
                const int bc = (wn + nj * 8 + grp) * 200 + kk + tg * 2;
                uint32_t bh0 = *(const uint32_t*)(Vth + bc);
                uint32_t bh1 = *(const uint32_t*)(Vth + bc + 8);
                uint32_t bl0 = *(const uint32_t*)(Vtl + bc);
                uint32_t bl1 = *(const uint32_t*)(Vtl + bc + 8);
                float* cc = acc[nj];
                mma16816(cc[0], cc[1], cc[2], cc[3], ah0, ah1, ah2, ah3, bh0, bh1);
                mma16816(cc[0], cc[1], cc[2], cc[3], al0, al1, al2, al3, bh0, bh1);
                mma16816(cc[0], cc[1], cc[2], cc[3], ah0, ah1, ah2, ah3, bl0, bl1);
            }
        }

        const long base = (long)(b * TDIM + q0) * DMODEL + h * DH;
        const int r0 = wm + grp, r1 = r0 + 8;
        #pragma unroll
        for (int nj = 0; nj < 2; nj++) {
            const int col = wn + nj * 8 + tg * 2;
            #pragma unroll
            for (int rr = 0; rr < 2; rr++) {
                const int row = rr ? r1 : r0;
                float v0 = acc[nj][rr * 2];
                float v1 = acc[nj][rr * 2 + 1];
                store_split2(g_aohi, g_aolo, base + (long)row * DMODEL + col, v0, v1);
            }
        }
    }
}

// ============================================================
// launch
// ============================================================
extern "C" void kernel_launch(void* const* d_in, const int* in_sizes, int n_in,
                              void* d_out, int out_size)
{
    const float* X  = (const float*)d_in[0];
    const float* Wq = (const float*)d_in[1];
    const float* Wk = (const float*)d_in[2];
    const float* Wv = (const float*)d_in[3];
    const float* Wo = (const float*)d_in[4];
    const float* bo = (const float*)d_in[5];
    float* out = (float*)d_out;

    cudaFuncSetAttribute(attn_kernel,
                         cudaFuncAttributeMaxDynamicSharedMemorySize,
                         ATTN_SMEM_BYTES);
    cudaFuncSetAttribute(qkv_mma_kernel,
                         cudaFuncAttributeMaxDynamicSharedMemorySize,
                         GEMM_SMEM_BYTES);
    cudaFuncSetAttribute(out_mma_kernel,
                         cudaFuncAttributeMaxDynamicSharedMemorySize,
                         GEMM_SMEM_BYTES);

    __nv_bfloat16 *xhi, *xlo, *whi, *wlo;
    cudaGetSymbolAddress((void**)&xhi, g_xhi);
    cudaGetSymbolAddress((void**)&xlo, g_xlo);
    cudaGetSymbolAddress((void**)&whi, g_whi);
    cudaGetSymbolAddress((void**)&wlo, g_wlo);

    rope_table_kernel<<<(TDIM * 32) / 256, 256>>>();
    cvt4_kernel<<<dim3((MTOT * DMODEL) / 1024, 5, 1), 256>>>(
        X, Wq, Wk, Wv, Wo, xhi, xlo, whi, wlo);

    qkv_mma_kernel<<<dim3(DMODEL / 256, MTOT / 128, 3), 512, GEMM_SMEM_BYTES>>>();
    attn_kernel<<<dim3(TDIM / 64, NH, BDIM), ATTN_THREADS, ATTN_SMEM_BYTES>>>();
    out_mma_kernel<<<dim3(DMODEL / 256, MTOT / 128, 1), 512, GEMM_SMEM_BYTES>>>(bo, out);
}